// round 2
// baseline (speedup 1.0000x reference)
#include <cuda_runtime.h>

#define BB 8
#define SS 4096
#define EE 768
#define JMAX 2048

// Scratch (device globals — no allocations allowed)
__device__ float g_Q[(size_t)BB * SS * EE];     // 100.7 MB
__device__ float g_K[(size_t)BB * JMAX * EE];   // 50.3 MB
__device__ float g_V[(size_t)BB * JMAX * EE];   // 50.3 MB
__device__ float g_P[(size_t)BB * SS * JMAX];   // 268 MB

#define INV_SQRT_DK 0.03608439182435161f

// Robust SEQ_idxes accessor: works whether the harness delivers the (B,2)
// tensor as int64 (dataset dtype) or downcast to int32.
// int64 little-endian layout as int32 words: [f0_lo, f0_hi(=0), s0_lo, 0, ...]
// int32 layout: [f0, s0, f1, s1, ...] with s0 in (2048, 4096] (never 0).
__device__ __forceinline__ int seq_first(const int* __restrict__ s, int b) {
    const bool is64 = (s[1] == 0);
    int v = is64 ? s[4 * b] : s[2 * b];
    // defensive clamp into the valid mask domain
    if (v < 1) v = 1;
    if (v > JMAX) v = JMAX;
    return v;
}

// ---------------------------------------------------------------------------
// Kernel 1: QKV projection.  out[row, n] = sum_k X[row,k] * W[n,k] + bias[n]
// NT gemm. which: 0=Q (all rows), 1=K, 2=V (rows limited to < first[b]).
// Tiles: BM=BN=128, BK=16. 256 threads, 8x8 per-thread micro-tile.
// ---------------------------------------------------------------------------
__global__ __launch_bounds__(256) void qkv_gemm(
    const float* __restrict__ X, const float* __restrict__ W,
    const float* __restrict__ bias, const int* __restrict__ seq,
    int which)
{
    const int tid = threadIdx.x;
    const int tx = tid & 15;
    const int ty = tid >> 4;

    float* out;
    int rpb;           // rows per batch in the output
    if (which == 0)      { out = g_Q; rpb = SS; }
    else if (which == 1) { out = g_K; rpb = JMAX; }
    else                 { out = g_V; rpb = JMAX; }

    const int tiles_per_batch = rpb >> 7;          // /128
    const int batch  = blockIdx.y / tiles_per_batch;
    const int row_in = (blockIdx.y % tiles_per_batch) << 7;
    const int col0   = blockIdx.x << 7;

    if (which != 0) {
        int first = seq_first(seq, batch);
        if (row_in >= first) return;               // tile entirely masked
    }

    const int xrow0 = batch * SS + row_in;

    __shared__ float As[16][128];
    __shared__ float Bs[16][128];

    float acc[8][8];
    #pragma unroll
    for (int i = 0; i < 8; i++)
        #pragma unroll
        for (int j = 0; j < 8; j++) acc[i][j] = 0.f;

    for (int k0 = 0; k0 < EE; k0 += 16) {
        // load A tile (X rows, transpose into smem) and B tile (W rows)
        #pragma unroll
        for (int v = tid; v < 512; v += 256) {
            int r = v >> 2;
            int c = (v & 3) << 2;
            float4 a = *(const float4*)&X[(size_t)(xrow0 + r) * EE + k0 + c];
            As[c + 0][r] = a.x; As[c + 1][r] = a.y;
            As[c + 2][r] = a.z; As[c + 3][r] = a.w;
            float4 w = *(const float4*)&W[(size_t)(col0 + r) * EE + k0 + c];
            Bs[c + 0][r] = w.x; Bs[c + 1][r] = w.y;
            Bs[c + 2][r] = w.z; Bs[c + 3][r] = w.w;
        }
        __syncthreads();

        #pragma unroll
        for (int kk = 0; kk < 16; kk++) {
            float4 a0 = *(const float4*)&As[kk][ty * 8];
            float4 a1 = *(const float4*)&As[kk][ty * 8 + 4];
            float4 b0 = *(const float4*)&Bs[kk][tx * 8];
            float4 b1 = *(const float4*)&Bs[kk][tx * 8 + 4];
            float av[8] = {a0.x,a0.y,a0.z,a0.w,a1.x,a1.y,a1.z,a1.w};
            float bv[8] = {b0.x,b0.y,b0.z,b0.w,b1.x,b1.y,b1.z,b1.w};
            #pragma unroll
            for (int i = 0; i < 8; i++)
                #pragma unroll
                for (int j = 0; j < 8; j++)
                    acc[i][j] = fmaf(av[i], bv[j], acc[i][j]);
        }
        __syncthreads();
    }

    // epilogue with bias
    float bv[8];
    #pragma unroll
    for (int j = 0; j < 8; j++) bv[j] = bias[col0 + tx * 8 + j];

    #pragma unroll
    for (int i = 0; i < 8; i++) {
        size_t orow = (size_t)batch * rpb + row_in + ty * 8 + i;
        float* op = &out[orow * EE + col0 + tx * 8];
        float4 o0 = make_float4(acc[i][0]+bv[0], acc[i][1]+bv[1],
                                acc[i][2]+bv[2], acc[i][3]+bv[3]);
        float4 o1 = make_float4(acc[i][4]+bv[4], acc[i][5]+bv[5],
                                acc[i][6]+bv[6], acc[i][7]+bv[7]);
        *(float4*)(op)     = o0;
        *(float4*)(op + 4) = o1;
    }
}

// ---------------------------------------------------------------------------
// Kernel 2: scores.  P[b,q,j] = inv_sqrt * sum_e Q[b,q,e] * K[b,j,e]
// NT gemm per batch. grid: x = JMAX/128, y = SS/128, z = B.
// ---------------------------------------------------------------------------
__global__ __launch_bounds__(256) void score_gemm(const int* __restrict__ seq)
{
    const int tid = threadIdx.x;
    const int tx = tid & 15;
    const int ty = tid >> 4;

    const int b    = blockIdx.z;
    const int col0 = blockIdx.x << 7;
    const int row0 = blockIdx.y << 7;

    const int first = seq_first(seq, b);
    if (col0 >= first) return;                    // tile entirely masked

    const float* Qb = g_Q + (size_t)b * SS * EE;
    const float* Kb = g_K + (size_t)b * JMAX * EE;

    __shared__ float As[16][128];
    __shared__ float Bs[16][128];

    float acc[8][8];
    #pragma unroll
    for (int i = 0; i < 8; i++)
        #pragma unroll
        for (int j = 0; j < 8; j++) acc[i][j] = 0.f;

    for (int k0 = 0; k0 < EE; k0 += 16) {
        #pragma unroll
        for (int v = tid; v < 512; v += 256) {
            int r = v >> 2;
            int c = (v & 3) << 2;
            float4 a = *(const float4*)&Qb[(size_t)(row0 + r) * EE + k0 + c];
            As[c + 0][r] = a.x; As[c + 1][r] = a.y;
            As[c + 2][r] = a.z; As[c + 3][r] = a.w;
            float4 kx = *(const float4*)&Kb[(size_t)(col0 + r) * EE + k0 + c];
            Bs[c + 0][r] = kx.x; Bs[c + 1][r] = kx.y;
            Bs[c + 2][r] = kx.z; Bs[c + 3][r] = kx.w;
        }
        __syncthreads();

        #pragma unroll
        for (int kk = 0; kk < 16; kk++) {
            float4 a0 = *(const float4*)&As[kk][ty * 8];
            float4 a1 = *(const float4*)&As[kk][ty * 8 + 4];
            float4 b0 = *(const float4*)&Bs[kk][tx * 8];
            float4 b1 = *(const float4*)&Bs[kk][tx * 8 + 4];
            float av[8] = {a0.x,a0.y,a0.z,a0.w,a1.x,a1.y,a1.z,a1.w};
            float bv[8] = {b0.x,b0.y,b0.z,b0.w,b1.x,b1.y,b1.z,b1.w};
            #pragma unroll
            for (int i = 0; i < 8; i++)
                #pragma unroll
                for (int j = 0; j < 8; j++)
                    acc[i][j] = fmaf(av[i], bv[j], acc[i][j]);
        }
        __syncthreads();
    }

    float* Pb = g_P + (size_t)b * SS * JMAX;
    #pragma unroll
    for (int i = 0; i < 8; i++) {
        float* pp = &Pb[(size_t)(row0 + ty * 8 + i) * JMAX + col0 + tx * 8];
        float4 o0 = make_float4(acc[i][0]*INV_SQRT_DK, acc[i][1]*INV_SQRT_DK,
                                acc[i][2]*INV_SQRT_DK, acc[i][3]*INV_SQRT_DK);
        float4 o1 = make_float4(acc[i][4]*INV_SQRT_DK, acc[i][5]*INV_SQRT_DK,
                                acc[i][6]*INV_SQRT_DK, acc[i][7]*INV_SQRT_DK);
        *(float4*)(pp)     = o0;
        *(float4*)(pp + 4) = o1;
    }
}

// ---------------------------------------------------------------------------
// Kernel 3: masked softmax over j in [1, first). Zeroes j=0 and pads
// [first, ceil16(first)) with zeros so pv_gemm needs no masking.
// One block per (b,q) row.
// ---------------------------------------------------------------------------
__global__ __launch_bounds__(256) void softmax_rows(const int* __restrict__ seq)
{
    const int b = blockIdx.x >> 12;     // / 4096
    const int q = blockIdx.x & 4095;
    const int first = seq_first(seq, b);
    float* row = g_P + ((size_t)b * SS + q) * JMAX;
    const int tid = threadIdx.x;

    __shared__ float red[256];

    float m = -1e30f;
    for (int j = 1 + tid; j < first; j += 256) m = fmaxf(m, row[j]);
    red[tid] = m;
    __syncthreads();
    #pragma unroll
    for (int s = 128; s > 0; s >>= 1) {
        if (tid < s) red[tid] = fmaxf(red[tid], red[tid + s]);
        __syncthreads();
    }
    m = red[0];
    __syncthreads();

    float l = 0.f;
    for (int j = 1 + tid; j < first; j += 256) l += expf(row[j] - m);
    red[tid] = l;
    __syncthreads();
    #pragma unroll
    for (int s = 128; s > 0; s >>= 1) {
        if (tid < s) red[tid] += red[tid + s];
        __syncthreads();
    }
    l = red[0];

    const float inv = 1.0f / l;
    for (int j = 1 + tid; j < first; j += 256)
        row[j] = expf(row[j] - m) * inv;

    const int kend = (first + 15) & ~15;
    for (int j = first + tid; j < kend; j += 256) row[j] = 0.f;
    if (tid == 0) row[0] = 0.f;
}

// ---------------------------------------------------------------------------
// Kernel 4: H = P @ V  (NN gemm per batch). K-dim = ceil16(first).
// grid: x = EE/128, y = SS/128, z = B.  Writes d_out directly.
// ---------------------------------------------------------------------------
__global__ __launch_bounds__(256) void pv_gemm(
    float* __restrict__ H, const int* __restrict__ seq)
{
    const int tid = threadIdx.x;
    const int tx = tid & 15;
    const int ty = tid >> 4;

    const int b    = blockIdx.z;
    const int col0 = blockIdx.x << 7;
    const int row0 = blockIdx.y << 7;

    const int first = seq_first(seq, b);
    const int kend  = (first + 15) & ~15;

    const float* Pb = g_P + (size_t)b * SS * JMAX;
    const float* Vb = g_V + (size_t)b * JMAX * EE;

    __shared__ float As[16][128];
    __shared__ float Bs[16][128];

    float acc[8][8];
    #pragma unroll
    for (int i = 0; i < 8; i++)
        #pragma unroll
        for (int j = 0; j < 8; j++) acc[i][j] = 0.f;

    for (int k0 = 0; k0 < kend; k0 += 16) {
        #pragma unroll
        for (int v = tid; v < 512; v += 256) {
            // A tile: P rows (transpose into smem)
            int r = v >> 2;
            int c = (v & 3) << 2;
            float4 a = *(const float4*)&Pb[(size_t)(row0 + r) * JMAX + k0 + c];
            As[c + 0][r] = a.x; As[c + 1][r] = a.y;
            As[c + 2][r] = a.z; As[c + 3][r] = a.w;
            // B tile: V rows (k-major in smem already — direct copy)
            int br = v >> 5;            // 0..15
            int bc = (v & 31) << 2;     // 0..124
            float4 w = *(const float4*)&Vb[(size_t)(k0 + br) * EE + col0 + bc];
            *(float4*)&Bs[br][bc] = w;
        }
        __syncthreads();

        #pragma unroll
        for (int kk = 0; kk < 16; kk++) {
            float4 a0 = *(const float4*)&As[kk][ty * 8];
            float4 a1 = *(const float4*)&As[kk][ty * 8 + 4];
            float4 b0 = *(const float4*)&Bs[kk][tx * 8];
            float4 b1 = *(const float4*)&Bs[kk][tx * 8 + 4];
            float av[8] = {a0.x,a0.y,a0.z,a0.w,a1.x,a1.y,a1.z,a1.w};
            float bv[8] = {b0.x,b0.y,b0.z,b0.w,b1.x,b1.y,b1.z,b1.w};
            #pragma unroll
            for (int i = 0; i < 8; i++)
                #pragma unroll
                for (int j = 0; j < 8; j++)
                    acc[i][j] = fmaf(av[i], bv[j], acc[i][j]);
        }
        __syncthreads();
    }

    float* Hb = H + (size_t)b * SS * EE;
    #pragma unroll
    for (int i = 0; i < 8; i++) {
        float* hp = &Hb[(size_t)(row0 + ty * 8 + i) * EE + col0 + tx * 8];
        *(float4*)(hp)     = make_float4(acc[i][0], acc[i][1], acc[i][2], acc[i][3]);
        *(float4*)(hp + 4) = make_float4(acc[i][4], acc[i][5], acc[i][6], acc[i][7]);
    }
}

// ---------------------------------------------------------------------------
extern "C" void kernel_launch(void* const* d_in, const int* in_sizes, int n_in,
                              void* d_out, int out_size)
{
    const float* ebd = (const float*)d_in[0];
    const int*   seq = (const int*)d_in[1];   // int64 or int32 — sniffed on device
    const float* Wq = (const float*)d_in[2];
    const float* bq = (const float*)d_in[3];
    const float* Wk = (const float*)d_in[4];
    const float* bk = (const float*)d_in[5];
    const float* Wv = (const float*)d_in[6];
    const float* bv = (const float*)d_in[7];
    float* H = (float*)d_out;

    // 1) projections
    qkv_gemm<<<dim3(EE / 128, BB * SS / 128), 256>>>(ebd, Wq, bq, seq, 0);
    qkv_gemm<<<dim3(EE / 128, BB * JMAX / 128), 256>>>(ebd, Wk, bk, seq, 1);
    qkv_gemm<<<dim3(EE / 128, BB * JMAX / 128), 256>>>(ebd, Wv, bv, seq, 2);

    // 2) scores
    score_gemm<<<dim3(JMAX / 128, SS / 128, BB), 256>>>(seq);

    // 3) masked softmax (+ zero-padding for PV)
    softmax_rows<<<BB * SS, 256>>>(seq);

    // 4) H = P @ V
    pv_gemm<<<dim3(EE / 128, SS / 128, BB), 256>>>(H, seq);
}

// round 4
// speedup vs baseline: 1.9564x; 1.9564x over previous
#include <cuda_runtime.h>
#include <cuda_bf16.h>
#include <cstdint>

#define BB 8
#define SS 4096
#define EE 768
#define JMAX 2048
#define INV_SQRT_DK 0.03608439182435161f

#define NX ((size_t)BB * SS * EE)     // 25.2M
#define NK ((size_t)BB * JMAX * EE)   // 12.6M
#define NP ((size_t)BB * SS * JMAX)   // 67.1M

// ---------------- scratch (device globals; no allocations allowed) ----------
__device__ __nv_bfloat16 g_Xhi[NX], g_Xlo[NX];
__device__ __nv_bfloat16 g_Wqh[EE * EE], g_Wql[EE * EE];
__device__ __nv_bfloat16 g_Wkh[EE * EE], g_Wkl[EE * EE];
__device__ __nv_bfloat16 g_Qhi[NX], g_Qlo[NX];
__device__ __nv_bfloat16 g_Khi[NK], g_Klo[NK];
__device__ __nv_bfloat16 g_Vth[NK], g_Vtl[NK];   // [b][e][token] transposed V splits
__device__ float g_P[NP];
__device__ __nv_bfloat16 g_Phi[NP], g_Plo[NP];

// ---------------- helpers ----------------------------------------------------
__device__ __forceinline__ uint32_t smem_to_u32(const void* p) {
    uint32_t a;
    asm("{ .reg .u64 t; cvta.to.shared.u64 t, %1; cvt.u32.u64 %0, t; }" : "=r"(a) : "l"(p));
    return a;
}
__device__ __forceinline__ int seq_first(const int* __restrict__ s, int b) {
    const bool is64 = (s[1] == 0);
    int v = is64 ? s[4 * b] : s[2 * b];
    if (v < 1) v = 1;
    if (v > JMAX) v = JMAX;
    return v;
}
__device__ __forceinline__ void split2(float v, __nv_bfloat16& h, __nv_bfloat16& l) {
    h = __float2bfloat16(v);
    l = __float2bfloat16(v - __bfloat162float(h));
}
__device__ __forceinline__ uint32_t packbf(__nv_bfloat16 a, __nv_bfloat16 b) {
    return (uint32_t)__bfloat16_as_ushort(a) | ((uint32_t)__bfloat16_as_ushort(b) << 16);
}

__device__ __forceinline__ void ldsm4(uint32_t* d, uint32_t a) {
    asm volatile("ldmatrix.sync.aligned.m8n8.x4.shared.b16 {%0,%1,%2,%3}, [%4];"
                 : "=r"(d[0]), "=r"(d[1]), "=r"(d[2]), "=r"(d[3]) : "r"(a));
}
__device__ __forceinline__ void mma_bf16(float* c, const uint32_t* a, uint32_t b0, uint32_t b1) {
    asm volatile(
        "mma.sync.aligned.m16n8k16.row.col.f32.bf16.bf16.f32 "
        "{%0,%1,%2,%3}, {%4,%5,%6,%7}, {%8,%9}, {%0,%1,%2,%3};"
        : "+f"(c[0]), "+f"(c[1]), "+f"(c[2]), "+f"(c[3])
        : "r"(a[0]), "r"(a[1]), "r"(a[2]), "r"(a[3]), "r"(b0), "r"(b1));
}
#define CP_ASYNC16(sa, ga) \
    asm volatile("cp.async.cg.shared.global [%0], [%1], 16;" :: "r"(sa), "l"(ga) : "memory")
#define CP_COMMIT() asm volatile("cp.async.commit_group;" ::: "memory")
#define CP_WAIT(n)  asm volatile("cp.async.wait_group %0;" :: "n"(n) : "memory")

// ---------------- kernel: fp32 -> (hi, lo) bf16 splits ------------------------
__global__ __launch_bounds__(256) void split_sel(const float* __restrict__ src,
                                                 int sel, size_t n4)
{
    size_t i = (size_t)blockIdx.x * 256 + threadIdx.x;
    if (i >= n4) return;
    __nv_bfloat16 *dh, *dl;
    if (sel == 0)      { dh = g_Xhi; dl = g_Xlo; }
    else if (sel == 1) { dh = g_Wqh; dl = g_Wql; }
    else               { dh = g_Wkh; dl = g_Wkl; }
    float4 v = ((const float4*)src)[i];
    __nv_bfloat16 h0, l0, h1, l1, h2, l2, h3, l3;
    split2(v.x, h0, l0); split2(v.y, h1, l1);
    split2(v.z, h2, l2); split2(v.w, h3, l3);
    ((uint2*)dh)[i] = make_uint2(packbf(h0, h1), packbf(h2, h3));
    ((uint2*)dl)[i] = make_uint2(packbf(l0, l1), packbf(l2, l3));
}

// ---------------- generic split-bf16 NT GEMM on mma.sync ---------------------
// D[128x128] = (Ahi+Alo)[128xK] * (Bhi+Blo)[128xK]^T  (3 bf16 products, f32 acc)
// smem: 4 tiles (Ah, Al, Bh, Bl), 128 rows x 64B data, 80B stride; 2 stages.
#define TSTRIDE 80
#define TILE_SM (128 * TSTRIDE)          // 10240
#define STAGE_SM (4 * TILE_SM)           // 40960
#define SMEM_TC (2 * STAGE_SM)           // 81920

#define MODE_PROJQ 0
#define MODE_PROJK 1
#define MODE_SCORE 2
#define MODE_PV    3

__global__ __launch_bounds__(256, 1) void tc_gemm(int mode, const int* __restrict__ seq,
                                                  const float* __restrict__ bias,
                                                  float* __restrict__ Hout)
{
    const int n0 = blockIdx.x << 7;
    int b = 0, first = 0, Kdim = EE;
    size_t arow, brow, orow;
    int lda, ldb, ldo = EE;
    const __nv_bfloat16 *Ah, *Al, *Bh, *Bl;
    float* outF = nullptr;
    __nv_bfloat16 *oHi = nullptr, *oLo = nullptr;
    float scale = 1.f;
    bool addb = false;

    if (mode == MODE_PROJQ) {
        arow = (size_t)blockIdx.y << 7; brow = n0; orow = arow;
        Ah = g_Xhi; Al = g_Xlo; lda = EE; Bh = g_Wqh; Bl = g_Wql; ldb = EE;
        oHi = g_Qhi; oLo = g_Qlo; ldo = EE; addb = true;
    } else if (mode == MODE_PROJK) {
        b = blockIdx.y >> 4;
        int tloc = (blockIdx.y & 15) << 7;
        first = seq_first(seq, b);
        if (tloc >= first) return;
        arow = (size_t)b * SS + tloc; brow = n0; orow = (size_t)b * JMAX + tloc;
        Ah = g_Xhi; Al = g_Xlo; lda = EE; Bh = g_Wkh; Bl = g_Wkl; ldb = EE;
        oHi = g_Khi; oLo = g_Klo; ldo = EE; addb = true;
    } else if (mode == MODE_SCORE) {
        b = blockIdx.z; first = seq_first(seq, b);
        if (n0 >= first) return;
        arow = (size_t)b * SS + ((size_t)blockIdx.y << 7);
        brow = (size_t)b * JMAX + n0;
        Ah = g_Qhi; Al = g_Qlo; lda = EE; Bh = g_Khi; Bl = g_Klo; ldb = EE;
        outF = g_P; ldo = JMAX; orow = arow; scale = INV_SQRT_DK;
    } else { // MODE_PV
        b = blockIdx.z; first = seq_first(seq, b);
        Kdim = (first + 63) & ~63;
        arow = (size_t)b * SS + ((size_t)blockIdx.y << 7);
        brow = (size_t)b * EE + n0;
        Ah = g_Phi; Al = g_Plo; lda = JMAX; Bh = g_Vth; Bl = g_Vtl; ldb = JMAX;
        outF = Hout; ldo = EE; orow = arow;
    }

    extern __shared__ char smem[];
    const uint32_t sbase = smem_to_u32(smem);
    const int tid  = threadIdx.x;
    const int lane = tid & 31, wid = tid >> 5;
    const int wm = wid >> 1, wn = wid & 1;          // 4 x 2 warp grid

    const char* gsrc[4] = { (const char*)(Ah + arow * lda), (const char*)(Al + arow * lda),
                            (const char*)(Bh + brow * ldb), (const char*)(Bl + brow * ldb) };
    const size_t ldby[4] = { (size_t)lda * 2, (size_t)lda * 2,
                             (size_t)ldb * 2, (size_t)ldb * 2 };

    auto load_stage = [&](int s, int ki) {
        const size_t k0b = (size_t)ki * 64;          // 32 bf16 = 64 bytes
        const uint32_t sb = sbase + s * STAGE_SM;
        #pragma unroll
        for (int j = 0; j < 8; j++) {
            int t = tid + j * 256;                   // 2048 chunks of 16B
            int tile = t >> 9, row = (t >> 2) & 127, c = t & 3;
            uint32_t sa = sb + tile * TILE_SM + row * TSTRIDE + c * 16;
            const char* ga = gsrc[tile] + (size_t)row * ldby[tile] + k0b + c * 16;
            CP_ASYNC16(sa, ga);
        }
    };

    float acc[2][8][4];
    #pragma unroll
    for (int mt = 0; mt < 2; mt++)
        #pragma unroll
        for (int nt = 0; nt < 8; nt++)
            #pragma unroll
            for (int r = 0; r < 4; r++) acc[mt][nt][r] = 0.f;

    const int kt = Kdim >> 5;                        // BK = 32

    load_stage(0, 0);
    CP_COMMIT();

    for (int i = 0; i < kt; i++) {
        const int cur = i & 1;
        if (i + 1 < kt) { load_stage(cur ^ 1, i + 1); CP_COMMIT(); CP_WAIT(1); }
        else            { CP_WAIT(0); }
        __syncthreads();

        const uint32_t sb = sbase + cur * STAGE_SM;
        #pragma unroll
        for (int ks = 0; ks < 2; ks++) {             // two k16 halves of BK=32
            uint32_t ah[2][4], alr[2][4];
            #pragma unroll
            for (int mt = 0; mt < 2; mt++) {
                uint32_t ra = sb + (wm * 32 + mt * 16 + (lane & 15)) * TSTRIDE
                            + ks * 32 + ((lane >> 4) << 4);
                ldsm4(ah[mt],  ra);
                ldsm4(alr[mt], ra + TILE_SM);
            }
            #pragma unroll
            for (int nt2 = 0; nt2 < 4; nt2++) {
                uint32_t rb = sb + 2 * TILE_SM
                            + (wn * 64 + nt2 * 16 + ((lane & 7) + ((lane >> 4) << 3))) * TSTRIDE
                            + ks * 32 + (((lane >> 3) & 1) << 4);
                uint32_t bh4[4], bl4[4];
                ldsm4(bh4, rb);
                ldsm4(bl4, rb + TILE_SM);
                #pragma unroll
                for (int mt = 0; mt < 2; mt++)
                    #pragma unroll
                    for (int nn = 0; nn < 2; nn++) {
                        float* c = acc[mt][nt2 * 2 + nn];
                        mma_bf16(c, ah[mt],  bh4[2 * nn], bh4[2 * nn + 1]);
                        mma_bf16(c, ah[mt],  bl4[2 * nn], bl4[2 * nn + 1]);
                        mma_bf16(c, alr[mt], bh4[2 * nn], bh4[2 * nn + 1]);
                    }
            }
        }
        __syncthreads();
    }

    // epilogue
    const int grp = lane >> 2, tig = lane & 3;
    #pragma unroll
    for (int mt = 0; mt < 2; mt++) {
        #pragma unroll
        for (int half = 0; half < 2; half++) {
            const size_t row = orow + wm * 32 + mt * 16 + grp + half * 8;
            #pragma unroll
            for (int nt = 0; nt < 8; nt++) {
                const int col = n0 + wn * 64 + nt * 8 + tig * 2;
                float v0 = acc[mt][nt][half * 2 + 0];
                float v1 = acc[mt][nt][half * 2 + 1];
                if (outF) {
                    *(float2*)&outF[row * ldo + col] = make_float2(v0 * scale, v1 * scale);
                } else {
                    if (addb) { v0 += bias[col]; v1 += bias[col + 1]; }
                    __nv_bfloat16 h0, l0, h1, l1;
                    split2(v0, h0, l0); split2(v1, h1, l1);
                    *(uint32_t*)&oHi[row * ldo + col] = packbf(h0, h1);
                    *(uint32_t*)&oLo[row * ldo + col] = packbf(l0, l1);
                }
            }
        }
    }
}

// ---------------- kernel: V projection (SIMT fp32), transposed split output --
__global__ __launch_bounds__(256) void v_gemm(
    const float* __restrict__ X, const float* __restrict__ W,
    const float* __restrict__ bias, const int* __restrict__ seq)
{
    const int tid = threadIdx.x;
    const int tx = tid & 15;
    const int ty = tid >> 4;

    const int b    = blockIdx.y >> 4;
    const int tloc = (blockIdx.y & 15) << 7;
    const int col0 = blockIdx.x << 7;
    const int first = seq_first(seq, b);
    if (tloc >= first) return;

    const int xrow0 = b * SS + tloc;

    __shared__ float As[16][128];
    __shared__ float Bs[16][128];

    float acc[8][8];
    #pragma unroll
    for (int i = 0; i < 8; i++)
        #pragma unroll
        for (int j = 0; j < 8; j++) acc[i][j] = 0.f;

    for (int k0 = 0; k0 < EE; k0 += 16) {
        #pragma unroll
        for (int v = tid; v < 512; v += 256) {
            int r = v >> 2;
            int c = (v & 3) << 2;
            float4 a = *(const float4*)&X[(size_t)(xrow0 + r) * EE + k0 + c];
            As[c + 0][r] = a.x; As[c + 1][r] = a.y;
            As[c + 2][r] = a.z; As[c + 3][r] = a.w;
            float4 wv = *(const float4*)&W[(size_t)(col0 + r) * EE + k0 + c];
            Bs[c + 0][r] = wv.x; Bs[c + 1][r] = wv.y;
            Bs[c + 2][r] = wv.z; Bs[c + 3][r] = wv.w;
        }
        __syncthreads();

        #pragma unroll
        for (int kk = 0; kk < 16; kk++) {
            float4 a0 = *(const float4*)&As[kk][ty * 8];
            float4 a1 = *(const float4*)&As[kk][ty * 8 + 4];
            float4 b0 = *(const float4*)&Bs[kk][tx * 8];
            float4 b1 = *(const float4*)&Bs[kk][tx * 8 + 4];
            float av[8] = {a0.x, a0.y, a0.z, a0.w, a1.x, a1.y, a1.z, a1.w};
            float bv[8] = {b0.x, b0.y, b0.z, b0.w, b1.x, b1.y, b1.z, b1.w};
            #pragma unroll
            for (int i = 0; i < 8; i++)
                #pragma unroll
                for (int j = 0; j < 8; j++)
                    acc[i][j] = fmaf(av[i], bv[j], acc[i][j]);
        }
        __syncthreads();
    }

    // transposed split write: Vt[b][e][token]
    const int tok0 = tloc + ty * 8;
    #pragma unroll
    for (int j = 0; j < 8; j++) {
        const int e = col0 + tx * 8 + j;
        const float be = bias[e];
        uint32_t hu[4], lu[4];
        #pragma unroll
        for (int pr = 0; pr < 4; pr++) {
            __nv_bfloat16 h0, l0, h1, l1;
            split2(acc[pr * 2 + 0][j] + be, h0, l0);
            split2(acc[pr * 2 + 1][j] + be, h1, l1);
            hu[pr] = packbf(h0, h1);
            lu[pr] = packbf(l0, l1);
        }
        const size_t off = ((size_t)b * EE + e) * JMAX + tok0;
        *(uint4*)&g_Vth[off] = make_uint4(hu[0], hu[1], hu[2], hu[3]);
        *(uint4*)&g_Vtl[off] = make_uint4(lu[0], lu[1], lu[2], lu[3]);
    }
}

// ---------------- kernel: masked softmax -> split bf16 P ---------------------
__global__ __launch_bounds__(256) void softmax_rows(const int* __restrict__ seq)
{
    const int b = blockIdx.x >> 12;
    const int q = blockIdx.x & 4095;
    const int first = seq_first(seq, b);
    const float* row = g_P + ((size_t)b * SS + q) * JMAX;
    const int tid = threadIdx.x;

    __shared__ float red[256];

    float m = -1e30f;
    for (int j = 1 + tid; j < first; j += 256) m = fmaxf(m, row[j]);
    red[tid] = m;
    __syncthreads();
    #pragma unroll
    for (int s = 128; s > 0; s >>= 1) {
        if (tid < s) red[tid] = fmaxf(red[tid], red[tid + s]);
        __syncthreads();
    }
    m = red[0];
    __syncthreads();

    float l = 0.f;
    for (int j = 1 + tid; j < first; j += 256) l += expf(row[j] - m);
    red[tid] = l;
    __syncthreads();
    #pragma unroll
    for (int s = 128; s > 0; s >>= 1) {
        if (tid < s) red[tid] += red[tid + s];
        __syncthreads();
    }
    const float inv = 1.0f / red[0];

    const int kpad = (first + 63) & ~63;
    const size_t ro = ((size_t)b * SS + q) * JMAX;
    for (int j = tid; j < kpad; j += 256) {
        float p = 0.f;
        if (j >= 1 && j < first) p = expf(row[j] - m) * inv;
        __nv_bfloat16 h, lo;
        split2(p, h, lo);
        g_Phi[ro + j] = h;
        g_Plo[ro + j] = lo;
    }
}

// ---------------------------------------------------------------------------
extern "C" void kernel_launch(void* const* d_in, const int* in_sizes, int n_in,
                              void* d_out, int out_size)
{
    const float* ebd = (const float*)d_in[0];
    const int*   seq = (const int*)d_in[1];
    const float* Wq = (const float*)d_in[2];
    const float* bq = (const float*)d_in[3];
    const float* Wk = (const float*)d_in[4];
    const float* bk = (const float*)d_in[5];
    const float* Wv = (const float*)d_in[6];
    const float* bv = (const float*)d_in[7];
    float* H = (float*)d_out;

    static bool attr_done = false;
    if (!attr_done) {
        cudaFuncSetAttribute(tc_gemm, cudaFuncAttributeMaxDynamicSharedMemorySize, SMEM_TC);
        attr_done = true;
    }

    // 0) fp32 -> split bf16 for X, Wq, Wk
    {
        size_t n4 = NX / 4;
        split_sel<<<(unsigned)((n4 + 255) / 256), 256>>>(ebd, 0, n4);
        size_t w4 = (size_t)EE * EE / 4;
        split_sel<<<(unsigned)((w4 + 255) / 256), 256>>>(Wq, 1, w4);
        split_sel<<<(unsigned)((w4 + 255) / 256), 256>>>(Wk, 2, w4);
    }

    // 1) projections
    tc_gemm<<<dim3(EE / 128, BB * SS / 128, 1), 256, SMEM_TC>>>(MODE_PROJQ, seq, bq, nullptr);
    tc_gemm<<<dim3(EE / 128, BB * (JMAX / 128), 1), 256, SMEM_TC>>>(MODE_PROJK, seq, bk, nullptr);
    v_gemm<<<dim3(EE / 128, BB * (JMAX / 128)), 256>>>(ebd, Wv, bv, seq);

    // 2) scores (fp32 out)
    tc_gemm<<<dim3(JMAX / 128, SS / 128, BB), 256, SMEM_TC>>>(MODE_SCORE, seq, nullptr, nullptr);

    // 3) masked softmax -> split bf16 P
    softmax_rows<<<BB * SS, 256>>>(seq);

    // 4) H = P @ V
    tc_gemm<<<dim3(EE / 128, SS / 128, BB), 256, SMEM_TC>>>(MODE_PV, seq, nullptr, H);
}

// round 5
// speedup vs baseline: 2.0726x; 1.0594x over previous
#include <cuda_runtime.h>
#include <cuda_bf16.h>
#include <cstdint>

#define BB 8
#define SS 4096
#define EE 768
#define JMAX 2048
#define INV_SQRT_DK 0.03608439182435161f

#define NX ((size_t)BB * SS * EE)     // 25.2M
#define NK ((size_t)BB * JMAX * EE)   // 12.6M
#define NP ((size_t)BB * SS * JMAX)   // 67.1M

// ---------------- scratch (device globals; no allocations allowed) ----------
__device__ __nv_bfloat16 g_Xhi[NX], g_Xlo[NX];
__device__ __nv_bfloat16 g_Wqh[EE * EE], g_Wql[EE * EE];
__device__ __nv_bfloat16 g_Wkh[EE * EE], g_Wkl[EE * EE];
__device__ __nv_bfloat16 g_Qhi[NX], g_Qlo[NX];
__device__ __nv_bfloat16 g_Khi[NK], g_Klo[NK];
__device__ __nv_bfloat16 g_Vth[NK], g_Vtl[NK];   // [b][e][token] transposed V splits
__device__ float g_P[NP];
__device__ __nv_bfloat16 g_Phi[NP], g_Plo[NP];

// ---------------- helpers ----------------------------------------------------
__device__ __forceinline__ uint32_t smem_to_u32(const void* p) {
    uint32_t a;
    asm("{ .reg .u64 t; cvta.to.shared.u64 t, %1; cvt.u32.u64 %0, t; }" : "=r"(a) : "l"(p));
    return a;
}
__device__ __forceinline__ int seq_first(const int* __restrict__ s, int b) {
    const bool is64 = (s[1] == 0);
    int v = is64 ? s[4 * b] : s[2 * b];
    if (v < 1) v = 1;
    if (v > JMAX) v = JMAX;
    return v;
}
__device__ __forceinline__ void split2(float v, __nv_bfloat16& h, __nv_bfloat16& l) {
    h = __float2bfloat16(v);
    l = __float2bfloat16(v - __bfloat162float(h));
}
__device__ __forceinline__ uint32_t packbf(__nv_bfloat16 a, __nv_bfloat16 b) {
    return (uint32_t)__bfloat16_as_ushort(a) | ((uint32_t)__bfloat16_as_ushort(b) << 16);
}

__device__ __forceinline__ void ldsm4(uint32_t* d, uint32_t a) {
    asm volatile("ldmatrix.sync.aligned.m8n8.x4.shared.b16 {%0,%1,%2,%3}, [%4];"
                 : "=r"(d[0]), "=r"(d[1]), "=r"(d[2]), "=r"(d[3]) : "r"(a));
}
__device__ __forceinline__ void mma_bf16(float* c, const uint32_t* a, uint32_t b0, uint32_t b1) {
    asm volatile(
        "mma.sync.aligned.m16n8k16.row.col.f32.bf16.bf16.f32 "
        "{%0,%1,%2,%3}, {%4,%5,%6,%7}, {%8,%9}, {%0,%1,%2,%3};"
        : "+f"(c[0]), "+f"(c[1]), "+f"(c[2]), "+f"(c[3])
        : "r"(a[0]), "r"(a[1]), "r"(a[2]), "r"(a[3]), "r"(b0), "r"(b1));
}
#define CP_ASYNC16(sa, ga) \
    asm volatile("cp.async.cg.shared.global [%0], [%1], 16;" :: "r"(sa), "l"(ga) : "memory")
#define CP_COMMIT() asm volatile("cp.async.commit_group;" ::: "memory")
#define CP_WAIT(n)  asm volatile("cp.async.wait_group %0;" :: "n"(n) : "memory")

// ---------------- kernel: fp32 -> (hi, lo) bf16 splits ------------------------
__global__ __launch_bounds__(256) void split_sel(const float* __restrict__ src,
                                                 int sel, size_t n4)
{
    size_t i = (size_t)blockIdx.x * 256 + threadIdx.x;
    if (i >= n4) return;
    __nv_bfloat16 *dh, *dl;
    if (sel == 0)      { dh = g_Xhi; dl = g_Xlo; }
    else if (sel == 1) { dh = g_Wqh; dl = g_Wql; }
    else               { dh = g_Wkh; dl = g_Wkl; }
    float4 v = ((const float4*)src)[i];
    __nv_bfloat16 h0, l0, h1, l1, h2, l2, h3, l3;
    split2(v.x, h0, l0); split2(v.y, h1, l1);
    split2(v.z, h2, l2); split2(v.w, h3, l3);
    ((uint2*)dh)[i] = make_uint2(packbf(h0, h1), packbf(h2, h3));
    ((uint2*)dl)[i] = make_uint2(packbf(l0, l1), packbf(l2, l3));
}

// ---------------- generic split-bf16 NT GEMM on mma.sync ---------------------
// D[256x128] = (Ahi+Alo)[256xK] * (Bhi+Blo)[128xK]^T  (3 bf16 products, f32 acc)
// smem per stage: Ah(256x80) Al(256x80) Bh(128x80) Bl(128x80) = 60 KB; 3 stages.
#define TSTRIDE 80
#define A_LO_OFF 20480
#define B_HI_OFF 40960
#define B_LO_OFF 51200
#define STAGE_SM 61440
#define SMEM_TC (3 * STAGE_SM)           // 184320

#define MODE_PROJQ 0
#define MODE_PROJK 1
#define MODE_SCORE 2
#define MODE_PV    3

__global__ __launch_bounds__(256, 1) void tc_gemm(int mode, const int* __restrict__ seq,
                                                  const float* __restrict__ bias,
                                                  float* __restrict__ Hout)
{
    const int n0 = blockIdx.x << 7;
    int b = 0, first = 0, Kdim = EE;
    size_t arow, brow, orow;
    int lda, ldb, ldo = EE;
    const __nv_bfloat16 *Ah, *Al, *Bh, *Bl;
    float* outF = nullptr;
    __nv_bfloat16 *oHi = nullptr, *oLo = nullptr;
    float scale = 1.f;
    bool addb = false;

    if (mode == MODE_PROJQ) {
        arow = (size_t)blockIdx.y << 8; brow = n0; orow = arow;
        Ah = g_Xhi; Al = g_Xlo; lda = EE; Bh = g_Wqh; Bl = g_Wql; ldb = EE;
        oHi = g_Qhi; oLo = g_Qlo; ldo = EE; addb = true;
    } else if (mode == MODE_PROJK) {
        b = blockIdx.y >> 3;
        int tloc = (blockIdx.y & 7) << 8;
        first = seq_first(seq, b);
        if (tloc >= first) return;
        arow = (size_t)b * SS + tloc; brow = n0; orow = (size_t)b * JMAX + tloc;
        Ah = g_Xhi; Al = g_Xlo; lda = EE; Bh = g_Wkh; Bl = g_Wkl; ldb = EE;
        oHi = g_Khi; oLo = g_Klo; ldo = EE; addb = true;
    } else if (mode == MODE_SCORE) {
        b = blockIdx.z; first = seq_first(seq, b);
        if (n0 >= first) return;
        arow = (size_t)b * SS + ((size_t)blockIdx.y << 8);
        brow = (size_t)b * JMAX + n0;
        Ah = g_Qhi; Al = g_Qlo; lda = EE; Bh = g_Khi; Bl = g_Klo; ldb = EE;
        outF = g_P; ldo = JMAX; orow = arow; scale = INV_SQRT_DK;
    } else { // MODE_PV
        b = blockIdx.z; first = seq_first(seq, b);
        Kdim = (first + 63) & ~63;
        arow = (size_t)b * SS + ((size_t)blockIdx.y << 8);
        brow = (size_t)b * EE + n0;
        Ah = g_Phi; Al = g_Plo; lda = JMAX; Bh = g_Vth; Bl = g_Vtl; ldb = JMAX;
        outF = Hout; ldo = EE; orow = arow;
    }

    extern __shared__ char smem[];
    const uint32_t sbase = smem_to_u32(smem);
    const int tid  = threadIdx.x;
    const int lane = tid & 31, wid = tid >> 5;
    const int wm = wid >> 1, wn = wid & 1;          // 4 x 2 warp grid, warp tile 64x64

    const char* gsrc[4] = { (const char*)(Ah + arow * lda), (const char*)(Al + arow * lda),
                            (const char*)(Bh + brow * ldb), (const char*)(Bl + brow * ldb) };
    const size_t ldby[4] = { (size_t)lda * 2, (size_t)lda * 2,
                             (size_t)ldb * 2, (size_t)ldb * 2 };
    const uint32_t smoff[4] = { 0, A_LO_OFF, B_HI_OFF, B_LO_OFF };

    const int kt = Kdim >> 5;                        // BK = 32

    auto load_stage = [&](int s, int ki) {
        const size_t k0b = (size_t)ki * 64;          // 32 bf16 = 64 bytes
        const uint32_t sb = sbase + s * STAGE_SM;
        #pragma unroll
        for (int j = 0; j < 12; j++) {               // 3072 chunks of 16B
            int t = tid + j * 256;
            int c = t & 3;
            int rr = t >> 2;                         // 0..767 concat row
            int tile, row;
            if (rr < 512) { tile = rr >> 8;          row = rr & 255; }
            else          { tile = 2 + ((rr - 512) >> 7); row = (rr - 512) & 127; }
            uint32_t sa = sb + smoff[tile] + row * TSTRIDE + c * 16;
            const char* ga = gsrc[tile] + (size_t)row * ldby[tile] + k0b + c * 16;
            CP_ASYNC16(sa, ga);
        }
    };

    float acc[4][8][4];
    #pragma unroll
    for (int mt = 0; mt < 4; mt++)
        #pragma unroll
        for (int nt = 0; nt < 8; nt++)
            #pragma unroll
            for (int r = 0; r < 4; r++) acc[mt][nt][r] = 0.f;

    // 3-stage pipeline, uniform (possibly empty) commit groups
    load_stage(0, 0); CP_COMMIT();
    if (kt > 1) load_stage(1, 1);
    CP_COMMIT();

    for (int i = 0; i < kt; i++) {
        CP_WAIT(1);
        __syncthreads();

        const uint32_t sb = sbase + (i % 3) * STAGE_SM;
        #pragma unroll
        for (int ks = 0; ks < 2; ks++) {             // two k16 halves of BK=32
            uint32_t ah[4][4], alr[4][4];
            #pragma unroll
            for (int mt = 0; mt < 4; mt++) {
                uint32_t ra = sb + (wm * 64 + mt * 16 + (lane & 15)) * TSTRIDE
                            + ks * 32 + ((lane >> 4) << 4);
                ldsm4(ah[mt],  ra);
                ldsm4(alr[mt], ra + A_LO_OFF);
            }
            #pragma unroll
            for (int nt2 = 0; nt2 < 4; nt2++) {
                uint32_t rb = sb + B_HI_OFF
                            + (wn * 64 + nt2 * 16 + ((lane & 7) + ((lane >> 4) << 3))) * TSTRIDE
                            + ks * 32 + (((lane >> 3) & 1) << 4);
                uint32_t bh4[4], bl4[4];
                ldsm4(bh4, rb);
                ldsm4(bl4, rb + (B_LO_OFF - B_HI_OFF));
                #pragma unroll
                for (int mt = 0; mt < 4; mt++)
                    #pragma unroll
                    for (int nn = 0; nn < 2; nn++) {
                        float* c = acc[mt][nt2 * 2 + nn];
                        mma_bf16(c, ah[mt],  bh4[2 * nn], bh4[2 * nn + 1]);
                        mma_bf16(c, ah[mt],  bl4[2 * nn], bl4[2 * nn + 1]);
                        mma_bf16(c, alr[mt], bh4[2 * nn], bh4[2 * nn + 1]);
                    }
            }
        }
        __syncthreads();
        if (i + 2 < kt) load_stage((i + 2) % 3, i + 2);
        CP_COMMIT();
    }

    // epilogue
    const int grp = lane >> 2, tig = lane & 3;
    #pragma unroll
    for (int mt = 0; mt < 4; mt++) {
        #pragma unroll
        for (int half = 0; half < 2; half++) {
            const size_t row = orow + wm * 64 + mt * 16 + grp + half * 8;
            #pragma unroll
            for (int nt = 0; nt < 8; nt++) {
                const int col = n0 + wn * 64 + nt * 8 + tig * 2;
                float v0 = acc[mt][nt][half * 2 + 0];
                float v1 = acc[mt][nt][half * 2 + 1];
                if (outF) {
                    *(float2*)&outF[row * ldo + col] = make_float2(v0 * scale, v1 * scale);
                } else {
                    if (addb) { v0 += bias[col]; v1 += bias[col + 1]; }
                    __nv_bfloat16 h0, l0, h1, l1;
                    split2(v0, h0, l0); split2(v1, h1, l1);
                    *(uint32_t*)&oHi[row * ldo + col] = packbf(h0, h1);
                    *(uint32_t*)&oLo[row * ldo + col] = packbf(l0, l1);
                }
            }
        }
    }
}

// ---------------- kernel: V projection (SIMT fp32), transposed split output --
__global__ __launch_bounds__(256) void v_gemm(
    const float* __restrict__ X, const float* __restrict__ W,
    const float* __restrict__ bias, const int* __restrict__ seq)
{
    const int tid = threadIdx.x;
    const int tx = tid & 15;
    const int ty = tid >> 4;

    const int b    = blockIdx.y >> 4;
    const int tloc = (blockIdx.y & 15) << 7;
    const int col0 = blockIdx.x << 7;
    const int first = seq_first(seq, b);
    if (tloc >= first) return;

    const int xrow0 = b * SS + tloc;

    __shared__ float As[16][128];
    __shared__ float Bs[16][128];

    float acc[8][8];
    #pragma unroll
    for (int i = 0; i < 8; i++)
        #pragma unroll
        for (int j = 0; j < 8; j++) acc[i][j] = 0.f;

    for (int k0 = 0; k0 < EE; k0 += 16) {
        #pragma unroll
        for (int v = tid; v < 512; v += 256) {
            int r = v >> 2;
            int c = (v & 3) << 2;
            float4 a = *(const float4*)&X[(size_t)(xrow0 + r) * EE + k0 + c];
            As[c + 0][r] = a.x; As[c + 1][r] = a.y;
            As[c + 2][r] = a.z; As[c + 3][r] = a.w;
            float4 wv = *(const float4*)&W[(size_t)(col0 + r) * EE + k0 + c];
            Bs[c + 0][r] = wv.x; Bs[c + 1][r] = wv.y;
            Bs[c + 2][r] = wv.z; Bs[c + 3][r] = wv.w;
        }
        __syncthreads();

        #pragma unroll
        for (int kk = 0; kk < 16; kk++) {
            float4 a0 = *(const float4*)&As[kk][ty * 8];
            float4 a1 = *(const float4*)&As[kk][ty * 8 + 4];
            float4 b0 = *(const float4*)&Bs[kk][tx * 8];
            float4 b1 = *(const float4*)&Bs[kk][tx * 8 + 4];
            float av[8] = {a0.x, a0.y, a0.z, a0.w, a1.x, a1.y, a1.z, a1.w};
            float bv[8] = {b0.x, b0.y, b0.z, b0.w, b1.x, b1.y, b1.z, b1.w};
            #pragma unroll
            for (int i = 0; i < 8; i++)
                #pragma unroll
                for (int j = 0; j < 8; j++)
                    acc[i][j] = fmaf(av[i], bv[j], acc[i][j]);
        }
        __syncthreads();
    }

    // transposed split write: Vt[b][e][token]
    const int tok0 = tloc + ty * 8;
    #pragma unroll
    for (int j = 0; j < 8; j++) {
        const int e = col0 + tx * 8 + j;
        const float be = bias[e];
        uint32_t hu[4], lu[4];
        #pragma unroll
        for (int pr = 0; pr < 4; pr++) {
            __nv_bfloat16 h0, l0, h1, l1;
            split2(acc[pr * 2 + 0][j] + be, h0, l0);
            split2(acc[pr * 2 + 1][j] + be, h1, l1);
            hu[pr] = packbf(h0, h1);
            lu[pr] = packbf(l0, l1);
        }
        const size_t off = ((size_t)b * EE + e) * JMAX + tok0;
        *(uint4*)&g_Vth[off] = make_uint4(hu[0], hu[1], hu[2], hu[3]);
        *(uint4*)&g_Vtl[off] = make_uint4(lu[0], lu[1], lu[2], lu[3]);
    }
}

// ---------------- kernel: masked softmax -> split bf16 P ---------------------
__global__ __launch_bounds__(256) void softmax_rows(const int* __restrict__ seq)
{
    const int b = blockIdx.x >> 12;
    const int q = blockIdx.x & 4095;
    const int first = seq_first(seq, b);
    const float* row = g_P + ((size_t)b * SS + q) * JMAX;
    const int tid = threadIdx.x;

    __shared__ float red[256];

    float m = -1e30f;
    for (int j = 1 + tid; j < first; j += 256) m = fmaxf(m, row[j]);
    red[tid] = m;
    __syncthreads();
    #pragma unroll
    for (int s = 128; s > 0; s >>= 1) {
        if (tid < s) red[tid] = fmaxf(red[tid], red[tid + s]);
        __syncthreads();
    }
    m = red[0];
    __syncthreads();

    float l = 0.f;
    for (int j = 1 + tid; j < first; j += 256) l += expf(row[j] - m);
    red[tid] = l;
    __syncthreads();
    #pragma unroll
    for (int s = 128; s > 0; s >>= 1) {
        if (tid < s) red[tid] += red[tid + s];
        __syncthreads();
    }
    const float inv = 1.0f / red[0];

    const int kpad = (first + 63) & ~63;
    const size_t ro = ((size_t)b * SS + q) * JMAX;
    for (int j = tid; j < kpad; j += 256) {
        float p = 0.f;
        if (j >= 1 && j < first) p = expf(row[j] - m) * inv;
        __nv_bfloat16 h, lo;
        split2(p, h, lo);
        g_Phi[ro + j] = h;
        g_Plo[ro + j] = lo;
    }
}

// ---------------------------------------------------------------------------
extern "C" void kernel_launch(void* const* d_in, const int* in_sizes, int n_in,
                              void* d_out, int out_size)
{
    const float* ebd = (const float*)d_in[0];
    const int*   seq = (const int*)d_in[1];
    const float* Wq = (const float*)d_in[2];
    const float* bq = (const float*)d_in[3];
    const float* Wk = (const float*)d_in[4];
    const float* bk = (const float*)d_in[5];
    const float* Wv = (const float*)d_in[6];
    const float* bv = (const float*)d_in[7];
    float* H = (float*)d_out;

    static bool attr_done = false;
    if (!attr_done) {
        cudaFuncSetAttribute(tc_gemm, cudaFuncAttributeMaxDynamicSharedMemorySize, SMEM_TC);
        attr_done = true;
    }

    // 0) fp32 -> split bf16 for X, Wq, Wk
    {
        size_t n4 = NX / 4;
        split_sel<<<(unsigned)((n4 + 255) / 256), 256>>>(ebd, 0, n4);
        size_t w4 = (size_t)EE * EE / 4;
        split_sel<<<(unsigned)((w4 + 255) / 256), 256>>>(Wq, 1, w4);
        split_sel<<<(unsigned)((w4 + 255) / 256), 256>>>(Wk, 2, w4);
    }

    // 1) projections
    tc_gemm<<<dim3(EE / 128, BB * SS / 256, 1), 256, SMEM_TC>>>(MODE_PROJQ, seq, bq, nullptr);
    tc_gemm<<<dim3(EE / 128, BB * (JMAX / 256), 1), 256, SMEM_TC>>>(MODE_PROJK, seq, bk, nullptr);
    v_gemm<<<dim3(EE / 128, BB * (JMAX / 128)), 256>>>(ebd, Wv, bv, seq);

    // 2) scores (fp32 out)
    tc_gemm<<<dim3(JMAX / 128, SS / 256, BB), 256, SMEM_TC>>>(MODE_SCORE, seq, nullptr, nullptr);

    // 3) masked softmax -> split bf16 P
    softmax_rows<<<BB * SS, 256>>>(seq);

    // 4) H = P @ V
    tc_gemm<<<dim3(EE / 128, SS / 256, BB), 256, SMEM_TC>>>(MODE_PV, seq, nullptr, H);
}

// round 6
// speedup vs baseline: 2.2798x; 1.1000x over previous
#include <cuda_runtime.h>
#include <cuda_bf16.h>
#include <cstdint>

#define BB 8
#define SS 4096
#define EE 768
#define JMAX 2048
#define INV_SQRT_DK 0.03608439182435161f

#define NX ((size_t)BB * SS * EE)     // 25.2M
#define NK ((size_t)BB * JMAX * EE)   // 12.6M
#define NP ((size_t)BB * SS * JMAX)   // 67.1M

// ---------------- scratch (device globals; no allocations allowed) ----------
__device__ __nv_bfloat16 g_Xhi[NX], g_Xlo[NX];
__device__ __nv_bfloat16 g_Wqh[EE * EE], g_Wql[EE * EE];
__device__ __nv_bfloat16 g_Wkh[EE * EE], g_Wkl[EE * EE];
__device__ __nv_bfloat16 g_Qhi[NX], g_Qlo[NX];
__device__ __nv_bfloat16 g_Khi[NK], g_Klo[NK];
__device__ __nv_bfloat16 g_Vth[NK], g_Vtl[NK];   // [b][e][token] transposed V splits
__device__ float g_P[NP];
__device__ __nv_bfloat16 g_Phi[NP], g_Plo[NP];

// ---------------- helpers ----------------------------------------------------
__device__ __forceinline__ uint32_t smem_to_u32(const void* p) {
    uint32_t a;
    asm("{ .reg .u64 t; cvta.to.shared.u64 t, %1; cvt.u32.u64 %0, t; }" : "=r"(a) : "l"(p));
    return a;
}
__device__ __forceinline__ int seq_first(const int* __restrict__ s, int b) {
    const bool is64 = (s[1] == 0);
    int v = is64 ? s[4 * b] : s[2 * b];
    if (v < 1) v = 1;
    if (v > JMAX) v = JMAX;
    return v;
}
__device__ __forceinline__ void split2(float v, __nv_bfloat16& h, __nv_bfloat16& l) {
    h = __float2bfloat16(v);
    l = __float2bfloat16(v - __bfloat162float(h));
}
__device__ __forceinline__ uint32_t packbf(__nv_bfloat16 a, __nv_bfloat16 b) {
    return (uint32_t)__bfloat16_as_ushort(a) | ((uint32_t)__bfloat16_as_ushort(b) << 16);
}

__device__ __forceinline__ void ldsm4(uint32_t* d, uint32_t a) {
    asm volatile("ldmatrix.sync.aligned.m8n8.x4.shared.b16 {%0,%1,%2,%3}, [%4];"
                 : "=r"(d[0]), "=r"(d[1]), "=r"(d[2]), "=r"(d[3]) : "r"(a));
}
__device__ __forceinline__ void mma_bf16(float* c, const uint32_t* a, uint32_t b0, uint32_t b1) {
    asm volatile(
        "mma.sync.aligned.m16n8k16.row.col.f32.bf16.bf16.f32 "
        "{%0,%1,%2,%3}, {%4,%5,%6,%7}, {%8,%9}, {%0,%1,%2,%3};"
        : "+f"(c[0]), "+f"(c[1]), "+f"(c[2]), "+f"(c[3])
        : "r"(a[0]), "r"(a[1]), "r"(a[2]), "r"(a[3]), "r"(b0), "r"(b1));
}
#define CP_ASYNC16(sa, ga) \
    asm volatile("cp.async.cg.shared.global [%0], [%1], 16;" :: "r"(sa), "l"(ga) : "memory")
#define CP_COMMIT() asm volatile("cp.async.commit_group;" ::: "memory")
#define CP_WAIT(n)  asm volatile("cp.async.wait_group %0;" :: "n"(n) : "memory")

// ---------------- kernel: fp32 -> (hi, lo) bf16 splits ------------------------
__global__ __launch_bounds__(256) void split_sel(const float* __restrict__ src,
                                                 int sel, size_t n4)
{
    size_t i = (size_t)blockIdx.x * 256 + threadIdx.x;
    if (i >= n4) return;
    __nv_bfloat16 *dh, *dl;
    if (sel == 0)      { dh = g_Xhi; dl = g_Xlo; }
    else if (sel == 1) { dh = g_Wqh; dl = g_Wql; }
    else               { dh = g_Wkh; dl = g_Wkl; }
    float4 v = ((const float4*)src)[i];
    __nv_bfloat16 h0, l0, h1, l1, h2, l2, h3, l3;
    split2(v.x, h0, l0); split2(v.y, h1, l1);
    split2(v.z, h2, l2); split2(v.w, h3, l3);
    ((uint2*)dh)[i] = make_uint2(packbf(h0, h1), packbf(h2, h3));
    ((uint2*)dl)[i] = make_uint2(packbf(l0, l1), packbf(l2, l3));
}

// ---------------- generic split-bf16 NT GEMM on mma.sync ---------------------
// D[128x128] = (Ahi+Alo)[128xK] * (Bhi+Blo)[128xK]^T  (3 bf16 products, f32 acc)
// smem: 4 tiles (Ah, Al, Bh, Bl), 128 rows x 64B data, 80B stride; 2 stages.
// 2 CTAs/SM (regs capped at 128) for latency hiding.
#define TSTRIDE 80
#define TILE_SM (128 * TSTRIDE)          // 10240
#define STAGE_SM (4 * TILE_SM)           // 40960
#define SMEM_TC (2 * STAGE_SM)           // 81920

#define MODE_PROJQ 0
#define MODE_PROJK 1
#define MODE_SCORE 2
#define MODE_PV    3

__global__ __launch_bounds__(256, 2) void tc_gemm(int mode, const int* __restrict__ seq,
                                                  const float* __restrict__ bias,
                                                  float* __restrict__ Hout)
{
    const int n0 = blockIdx.x << 7;
    int b = 0, first = 0, Kdim = EE;
    size_t arow, brow, orow;
    int lda, ldb, ldo = EE;
    const __nv_bfloat16 *Ah, *Al, *Bh, *Bl;
    float* outF = nullptr;
    __nv_bfloat16 *oHi = nullptr, *oLo = nullptr;
    float scale = 1.f;
    bool addb = false;

    if (mode == MODE_PROJQ) {
        arow = (size_t)blockIdx.y << 7; brow = n0; orow = arow;
        Ah = g_Xhi; Al = g_Xlo; lda = EE; Bh = g_Wqh; Bl = g_Wql; ldb = EE;
        oHi = g_Qhi; oLo = g_Qlo; ldo = EE; addb = true;
    } else if (mode == MODE_PROJK) {
        b = blockIdx.y >> 4;
        int tloc = (blockIdx.y & 15) << 7;
        first = seq_first(seq, b);
        if (tloc >= first) return;
        arow = (size_t)b * SS + tloc; brow = n0; orow = (size_t)b * JMAX + tloc;
        Ah = g_Xhi; Al = g_Xlo; lda = EE; Bh = g_Wkh; Bl = g_Wkl; ldb = EE;
        oHi = g_Khi; oLo = g_Klo; ldo = EE; addb = true;
    } else if (mode == MODE_SCORE) {
        b = blockIdx.z; first = seq_first(seq, b);
        if (n0 >= first) return;
        arow = (size_t)b * SS + ((size_t)blockIdx.y << 7);
        brow = (size_t)b * JMAX + n0;
        Ah = g_Qhi; Al = g_Qlo; lda = EE; Bh = g_Khi; Bl = g_Klo; ldb = EE;
        outF = g_P; ldo = JMAX; orow = arow; scale = INV_SQRT_DK;
    } else { // MODE_PV
        b = blockIdx.z; first = seq_first(seq, b);
        Kdim = (first + 63) & ~63;
        arow = (size_t)b * SS + ((size_t)blockIdx.y << 7);
        brow = (size_t)b * EE + n0;
        Ah = g_Phi; Al = g_Plo; lda = JMAX; Bh = g_Vth; Bl = g_Vtl; ldb = JMAX;
        outF = Hout; ldo = EE; orow = arow;
    }

    extern __shared__ char smem[];
    const uint32_t sbase = smem_to_u32(smem);
    const int tid  = threadIdx.x;
    const int lane = tid & 31, wid = tid >> 5;
    const int wm = wid >> 1, wn = wid & 1;          // 4 x 2 warp grid, warp tile 32x64

    const char* gsrc[4] = { (const char*)(Ah + arow * lda), (const char*)(Al + arow * lda),
                            (const char*)(Bh + brow * ldb), (const char*)(Bl + brow * ldb) };
    const size_t ldby[4] = { (size_t)lda * 2, (size_t)lda * 2,
                             (size_t)ldb * 2, (size_t)ldb * 2 };

    auto load_stage = [&](int s, int ki) {
        const size_t k0b = (size_t)ki * 64;          // 32 bf16 = 64 bytes
        const uint32_t sb = sbase + s * STAGE_SM;
        #pragma unroll
        for (int j = 0; j < 8; j++) {
            int t = tid + j * 256;                   // 2048 chunks of 16B
            int tile = t >> 9, row = (t >> 2) & 127, c = t & 3;
            uint32_t sa = sb + tile * TILE_SM + row * TSTRIDE + c * 16;
            const char* ga = gsrc[tile] + (size_t)row * ldby[tile] + k0b + c * 16;
            CP_ASYNC16(sa, ga);
        }
    };

    float acc[2][8][4];
    #pragma unroll
    for (int mt = 0; mt < 2; mt++)
        #pragma unroll
        for (int nt = 0; nt < 8; nt++)
            #pragma unroll
            for (int r = 0; r < 4; r++) acc[mt][nt][r] = 0.f;

    const int kt = Kdim >> 5;                        // BK = 32

    load_stage(0, 0);
    CP_COMMIT();

    for (int i = 0; i < kt; i++) {
        const int cur = i & 1;
        if (i + 1 < kt) { load_stage(cur ^ 1, i + 1); CP_COMMIT(); CP_WAIT(1); }
        else            { CP_WAIT(0); }
        __syncthreads();

        const uint32_t sb = sbase + cur * STAGE_SM;
        #pragma unroll
        for (int ks = 0; ks < 2; ks++) {             // two k16 halves of BK=32
            // preload ALL fragments for this k16 step
            uint32_t ah[2][4], alr[2][4];
            #pragma unroll
            for (int mt = 0; mt < 2; mt++) {
                uint32_t ra = sb + (wm * 32 + mt * 16 + (lane & 15)) * TSTRIDE
                            + ks * 32 + ((lane >> 4) << 4);
                ldsm4(ah[mt],  ra);
                ldsm4(alr[mt], ra + TILE_SM);
            }
            uint32_t bh4[4][4], bl4[4][4];
            #pragma unroll
            for (int nt2 = 0; nt2 < 4; nt2++) {
                uint32_t rb = sb + 2 * TILE_SM
                            + (wn * 64 + nt2 * 16 + ((lane & 7) + ((lane >> 4) << 3))) * TSTRIDE
                            + ks * 32 + (((lane >> 3) & 1) << 4);
                ldsm4(bh4[nt2], rb);
                ldsm4(bl4[nt2], rb + TILE_SM);
            }
            // product loop OUTERMOST: same-accumulator reuse distance = 16 MMAs
            #pragma unroll
            for (int p = 0; p < 3; p++) {
                #pragma unroll
                for (int mt = 0; mt < 2; mt++)
                    #pragma unroll
                    for (int nt2 = 0; nt2 < 4; nt2++)
                        #pragma unroll
                        for (int nn = 0; nn < 2; nn++) {
                            float* c = acc[mt][nt2 * 2 + nn];
                            const uint32_t* a = (p == 2) ? alr[mt] : ah[mt];
                            const uint32_t* bb = (p == 1) ? bl4[nt2] : bh4[nt2];
                            mma_bf16(c, a, bb[2 * nn], bb[2 * nn + 1]);
                        }
            }
        }
        __syncthreads();
    }

    // epilogue
    const int grp = lane >> 2, tig = lane & 3;
    #pragma unroll
    for (int mt = 0; mt < 2; mt++) {
        #pragma unroll
        for (int half = 0; half < 2; half++) {
            const size_t row = orow + wm * 32 + mt * 16 + grp + half * 8;
            #pragma unroll
            for (int nt = 0; nt < 8; nt++) {
                const int col = n0 + wn * 64 + nt * 8 + tig * 2;
                float v0 = acc[mt][nt][half * 2 + 0];
                float v1 = acc[mt][nt][half * 2 + 1];
                if (outF) {
                    *(float2*)&outF[row * ldo + col] = make_float2(v0 * scale, v1 * scale);
                } else {
                    if (addb) { v0 += bias[col]; v1 += bias[col + 1]; }
                    __nv_bfloat16 h0, l0, h1, l1;
                    split2(v0, h0, l0); split2(v1, h1, l1);
                    *(uint32_t*)&oHi[row * ldo + col] = packbf(h0, h1);
                    *(uint32_t*)&oLo[row * ldo + col] = packbf(l0, l1);
                }
            }
        }
    }
}

// ---------------- kernel: V projection (SIMT fp32), transposed split output --
__global__ __launch_bounds__(256) void v_gemm(
    const float* __restrict__ X, const float* __restrict__ W,
    const float* __restrict__ bias, const int* __restrict__ seq)
{
    const int tid = threadIdx.x;
    const int tx = tid & 15;
    const int ty = tid >> 4;

    const int b    = blockIdx.y >> 4;
    const int tloc = (blockIdx.y & 15) << 7;
    const int col0 = blockIdx.x << 7;
    const int first = seq_first(seq, b);
    if (tloc >= first) return;

    const int xrow0 = b * SS + tloc;

    __shared__ float As[16][128];
    __shared__ float Bs[16][128];

    float acc[8][8];
    #pragma unroll
    for (int i = 0; i < 8; i++)
        #pragma unroll
        for (int j = 0; j < 8; j++) acc[i][j] = 0.f;

    for (int k0 = 0; k0 < EE; k0 += 16) {
        #pragma unroll
        for (int v = tid; v < 512; v += 256) {
            int r = v >> 2;
            int c = (v & 3) << 2;
            float4 a = *(const float4*)&X[(size_t)(xrow0 + r) * EE + k0 + c];
            As[c + 0][r] = a.x; As[c + 1][r] = a.y;
            As[c + 2][r] = a.z; As[c + 3][r] = a.w;
            float4 wv = *(const float4*)&W[(size_t)(col0 + r) * EE + k0 + c];
            Bs[c + 0][r] = wv.x; Bs[c + 1][r] = wv.y;
            Bs[c + 2][r] = wv.z; Bs[c + 3][r] = wv.w;
        }
        __syncthreads();

        #pragma unroll
        for (int kk = 0; kk < 16; kk++) {
            float4 a0 = *(const float4*)&As[kk][ty * 8];
            float4 a1 = *(const float4*)&As[kk][ty * 8 + 4];
            float4 b0 = *(const float4*)&Bs[kk][tx * 8];
            float4 b1 = *(const float4*)&Bs[kk][tx * 8 + 4];
            float av[8] = {a0.x, a0.y, a0.z, a0.w, a1.x, a1.y, a1.z, a1.w};
            float bv[8] = {b0.x, b0.y, b0.z, b0.w, b1.x, b1.y, b1.z, b1.w};
            #pragma unroll
            for (int i = 0; i < 8; i++)
                #pragma unroll
                for (int j = 0; j < 8; j++)
                    acc[i][j] = fmaf(av[i], bv[j], acc[i][j]);
        }
        __syncthreads();
    }

    // transposed split write: Vt[b][e][token]
    const int tok0 = tloc + ty * 8;
    #pragma unroll
    for (int j = 0; j < 8; j++) {
        const int e = col0 + tx * 8 + j;
        const float be = bias[e];
        uint32_t hu[4], lu[4];
        #pragma unroll
        for (int pr = 0; pr < 4; pr++) {
            __nv_bfloat16 h0, l0, h1, l1;
            split2(acc[pr * 2 + 0][j] + be, h0, l0);
            split2(acc[pr * 2 + 1][j] + be, h1, l1);
            hu[pr] = packbf(h0, h1);
            lu[pr] = packbf(l0, l1);
        }
        const size_t off = ((size_t)b * EE + e) * JMAX + tok0;
        *(uint4*)&g_Vth[off] = make_uint4(hu[0], hu[1], hu[2], hu[3]);
        *(uint4*)&g_Vtl[off] = make_uint4(lu[0], lu[1], lu[2], lu[3]);
    }
}

// ---------------- kernel: masked softmax -> split bf16 P ---------------------
__global__ __launch_bounds__(256) void softmax_rows(const int* __restrict__ seq)
{
    const int b = blockIdx.x >> 12;
    const int q = blockIdx.x & 4095;
    const int first = seq_first(seq, b);
    const float* row = g_P + ((size_t)b * SS + q) * JMAX;
    const int tid = threadIdx.x;

    __shared__ float red[256];

    float m = -1e30f;
    for (int j = 1 + tid; j < first; j += 256) m = fmaxf(m, row[j]);
    red[tid] = m;
    __syncthreads();
    #pragma unroll
    for (int s = 128; s > 0; s >>= 1) {
        if (tid < s) red[tid] = fmaxf(red[tid], red[tid + s]);
        __syncthreads();
    }
    m = red[0];
    __syncthreads();

    float l = 0.f;
    for (int j = 1 + tid; j < first; j += 256) l += expf(row[j] - m);
    red[tid] = l;
    __syncthreads();
    #pragma unroll
    for (int s = 128; s > 0; s >>= 1) {
        if (tid < s) red[tid] += red[tid + s];
        __syncthreads();
    }
    const float inv = 1.0f / red[0];

    const int kpad = (first + 63) & ~63;
    const size_t ro = ((size_t)b * SS + q) * JMAX;
    for (int j = tid; j < kpad; j += 256) {
        float p = 0.f;
        if (j >= 1 && j < first) p = expf(row[j] - m) * inv;
        __nv_bfloat16 h, lo;
        split2(p, h, lo);
        g_Phi[ro + j] = h;
        g_Plo[ro + j] = lo;
    }
}

// ---------------------------------------------------------------------------
extern "C" void kernel_launch(void* const* d_in, const int* in_sizes, int n_in,
                              void* d_out, int out_size)
{
    const float* ebd = (const float*)d_in[0];
    const int*   seq = (const int*)d_in[1];
    const float* Wq = (const float*)d_in[2];
    const float* bq = (const float*)d_in[3];
    const float* Wk = (const float*)d_in[4];
    const float* bk = (const float*)d_in[5];
    const float* Wv = (const float*)d_in[6];
    const float* bv = (const float*)d_in[7];
    float* H = (float*)d_out;

    static bool attr_done = false;
    if (!attr_done) {
        cudaFuncSetAttribute(tc_gemm, cudaFuncAttributeMaxDynamicSharedMemorySize, SMEM_TC);
        attr_done = true;
    }

    // 0) fp32 -> split bf16 for X, Wq, Wk
    {
        size_t n4 = NX / 4;
        split_sel<<<(unsigned)((n4 + 255) / 256), 256>>>(ebd, 0, n4);
        size_t w4 = (size_t)EE * EE / 4;
        split_sel<<<(unsigned)((w4 + 255) / 256), 256>>>(Wq, 1, w4);
        split_sel<<<(unsigned)((w4 + 255) / 256), 256>>>(Wk, 2, w4);
    }

    // 1) projections
    tc_gemm<<<dim3(EE / 128, BB * SS / 128, 1), 256, SMEM_TC>>>(MODE_PROJQ, seq, bq, nullptr);
    tc_gemm<<<dim3(EE / 128, BB * (JMAX / 128), 1), 256, SMEM_TC>>>(MODE_PROJK, seq, bk, nullptr);
    v_gemm<<<dim3(EE / 128, BB * (JMAX / 128)), 256>>>(ebd, Wv, bv, seq);

    // 2) scores (fp32 out)
    tc_gemm<<<dim3(JMAX / 128, SS / 128, BB), 256, SMEM_TC>>>(MODE_SCORE, seq, nullptr, nullptr);

    // 3) masked softmax -> split bf16 P
    softmax_rows<<<BB * SS, 256>>>(seq);

    // 4) H = P @ V
    tc_gemm<<<dim3(EE / 128, SS / 128, BB), 256, SMEM_TC>>>(MODE_PV, seq, nullptr, H);
}

// round 7
// speedup vs baseline: 2.4159x; 1.0597x over previous
#include <cuda_runtime.h>
#include <cuda_bf16.h>
#include <cstdint>

#define BB 8
#define SS 4096
#define EE 768
#define JMAX 2048
#define INV_SQRT_DK 0.03608439182435161f

#define NX ((size_t)BB * SS * EE)     // 25.2M
#define NK ((size_t)BB * JMAX * EE)   // 12.6M
#define NP ((size_t)BB * SS * JMAX)   // 67.1M

// ---------------- scratch (device globals; no allocations allowed) ----------
__device__ __nv_bfloat16 g_Xhi[NX], g_Xlo[NX];
__device__ __nv_bfloat16 g_Wqh[EE * EE], g_Wql[EE * EE];
__device__ __nv_bfloat16 g_Wkh[EE * EE], g_Wkl[EE * EE];
__device__ __nv_bfloat16 g_Qhi[NX], g_Qlo[NX];
__device__ __nv_bfloat16 g_Khi[NK], g_Klo[NK];
__device__ __nv_bfloat16 g_Vth[NK], g_Vtl[NK];   // [b][e][token] transposed V splits
__device__ float g_P[NP];
__device__ __nv_bfloat16 g_Phi[NP], g_Plo[NP];

// ---------------- helpers ----------------------------------------------------
__device__ __forceinline__ uint32_t smem_to_u32(const void* p) {
    uint32_t a;
    asm("{ .reg .u64 t; cvta.to.shared.u64 t, %1; cvt.u32.u64 %0, t; }" : "=r"(a) : "l"(p));
    return a;
}
__device__ __forceinline__ int seq_first(const int* __restrict__ s, int b) {
    const bool is64 = (s[1] == 0);
    int v = is64 ? s[4 * b] : s[2 * b];
    if (v < 1) v = 1;
    if (v > JMAX) v = JMAX;
    return v;
}
__device__ __forceinline__ void split2(float v, __nv_bfloat16& h, __nv_bfloat16& l) {
    h = __float2bfloat16(v);
    l = __float2bfloat16(v - __bfloat162float(h));
}
__device__ __forceinline__ uint32_t packbf(__nv_bfloat16 a, __nv_bfloat16 b) {
    return (uint32_t)__bfloat16_as_ushort(a) | ((uint32_t)__bfloat16_as_ushort(b) << 16);
}

__device__ __forceinline__ void ldsm4(uint32_t* d, uint32_t a) {
    asm volatile("ldmatrix.sync.aligned.m8n8.x4.shared.b16 {%0,%1,%2,%3}, [%4];"
                 : "=r"(d[0]), "=r"(d[1]), "=r"(d[2]), "=r"(d[3]) : "r"(a));
}
__device__ __forceinline__ void mma_bf16(float* c, const uint32_t* a, uint32_t b0, uint32_t b1) {
    asm volatile(
        "mma.sync.aligned.m16n8k16.row.col.f32.bf16.bf16.f32 "
        "{%0,%1,%2,%3}, {%4,%5,%6,%7}, {%8,%9}, {%0,%1,%2,%3};"
        : "+f"(c[0]), "+f"(c[1]), "+f"(c[2]), "+f"(c[3])
        : "r"(a[0]), "r"(a[1]), "r"(a[2]), "r"(a[3]), "r"(b0), "r"(b1));
}
#define CP_ASYNC16(sa, ga) \
    asm volatile("cp.async.cg.shared.global [%0], [%1], 16;" :: "r"(sa), "l"(ga) : "memory")
#define CP_COMMIT() asm volatile("cp.async.commit_group;" ::: "memory")
#define CP_WAIT(n)  asm volatile("cp.async.wait_group %0;" :: "n"(n) : "memory")

// ---------------- kernel: fp32 -> (hi, lo) bf16 splits ------------------------
__global__ __launch_bounds__(256) void split_sel(const float* __restrict__ src,
                                                 int sel, size_t n4)
{
    size_t i = (size_t)blockIdx.x * 256 + threadIdx.x;
    if (i >= n4) return;
    __nv_bfloat16 *dh, *dl;
    if (sel == 0)      { dh = g_Xhi; dl = g_Xlo; }
    else if (sel == 1) { dh = g_Wqh; dl = g_Wql; }
    else               { dh = g_Wkh; dl = g_Wkl; }
    float4 v = ((const float4*)src)[i];
    __nv_bfloat16 h0, l0, h1, l1, h2, l2, h3, l3;
    split2(v.x, h0, l0); split2(v.y, h1, l1);
    split2(v.z, h2, l2); split2(v.w, h3, l3);
    ((uint2*)dh)[i] = make_uint2(packbf(h0, h1), packbf(h2, h3));
    ((uint2*)dl)[i] = make_uint2(packbf(l0, l1), packbf(l2, l3));
}

// ---------------- generic split-bf16 NT GEMM on mma.sync ---------------------
// D[128x128] = (Ahi+Alo)[128xK] * (Bhi+Blo)[128xK]^T  (3 bf16 products, f32 acc)
// 128 threads (4 warps, 2x2 grid, 64x64 warp tile), 2 CTAs/SM.
// smem: 4 tiles (Ah, Al, Bh, Bl), 128 rows x 64B data, 80B stride; 2 stages.
#define TSTRIDE 80
#define TILE_SM (128 * TSTRIDE)          // 10240
#define STAGE_SM (4 * TILE_SM)           // 40960
#define SMEM_TC (2 * STAGE_SM)           // 81920

#define MODE_PROJQ 0
#define MODE_PROJK 1
#define MODE_SCORE 2
#define MODE_PV    3

__global__ __launch_bounds__(128, 2) void tc_gemm(int mode, const int* __restrict__ seq,
                                                  const float* __restrict__ bias,
                                                  float* __restrict__ Hout)
{
    const int n0 = blockIdx.x << 7;
    int b = 0, first = 0, Kdim = EE;
    size_t arow, brow, orow;
    int lda, ldb, ldo = EE;
    const __nv_bfloat16 *Ah, *Al, *Bh, *Bl;
    float* outF = nullptr;
    __nv_bfloat16 *oHi = nullptr, *oLo = nullptr;
    float scale = 1.f;
    bool addb = false;

    if (mode == MODE_PROJQ) {
        arow = (size_t)blockIdx.y << 7; brow = n0; orow = arow;
        Ah = g_Xhi; Al = g_Xlo; lda = EE; Bh = g_Wqh; Bl = g_Wql; ldb = EE;
        oHi = g_Qhi; oLo = g_Qlo; ldo = EE; addb = true;
    } else if (mode == MODE_PROJK) {
        b = blockIdx.y >> 4;
        int tloc = (blockIdx.y & 15) << 7;
        first = seq_first(seq, b);
        if (tloc >= first) return;
        arow = (size_t)b * SS + tloc; brow = n0; orow = (size_t)b * JMAX + tloc;
        Ah = g_Xhi; Al = g_Xlo; lda = EE; Bh = g_Wkh; Bl = g_Wkl; ldb = EE;
        oHi = g_Khi; oLo = g_Klo; ldo = EE; addb = true;
    } else if (mode == MODE_SCORE) {
        b = blockIdx.z; first = seq_first(seq, b);
        if (n0 >= first) return;
        arow = (size_t)b * SS + ((size_t)blockIdx.y << 7);
        brow = (size_t)b * JMAX + n0;
        Ah = g_Qhi; Al = g_Qlo; lda = EE; Bh = g_Khi; Bl = g_Klo; ldb = EE;
        outF = g_P; ldo = JMAX; orow = arow; scale = INV_SQRT_DK;
    } else { // MODE_PV
        b = blockIdx.z; first = seq_first(seq, b);
        Kdim = (first + 63) & ~63;
        arow = (size_t)b * SS + ((size_t)blockIdx.y << 7);
        brow = (size_t)b * EE + n0;
        Ah = g_Phi; Al = g_Plo; lda = JMAX; Bh = g_Vth; Bl = g_Vtl; ldb = JMAX;
        outF = Hout; ldo = EE; orow = arow;
    }

    extern __shared__ char smem[];
    const uint32_t sbase = smem_to_u32(smem);
    const int tid  = threadIdx.x;
    const int lane = tid & 31, wid = tid >> 5;
    const int wm = wid >> 1, wn = wid & 1;          // 2 x 2 warp grid, warp tile 64x64

    const char* gsrc[4] = { (const char*)(Ah + arow * lda), (const char*)(Al + arow * lda),
                            (const char*)(Bh + brow * ldb), (const char*)(Bl + brow * ldb) };
    const size_t ldby[4] = { (size_t)lda * 2, (size_t)lda * 2,
                             (size_t)ldb * 2, (size_t)ldb * 2 };

    auto load_stage = [&](int s, int ki) {
        const size_t k0b = (size_t)ki * 64;          // 32 bf16 = 64 bytes
        const uint32_t sb = sbase + s * STAGE_SM;
        #pragma unroll
        for (int j = 0; j < 16; j++) {
            int t = tid + j * 128;                   // 2048 chunks of 16B
            int tile = t >> 9, row = (t >> 2) & 127, c = t & 3;
            uint32_t sa = sb + tile * TILE_SM + row * TSTRIDE + c * 16;
            const char* ga = gsrc[tile] + (size_t)row * ldby[tile] + k0b + c * 16;
            CP_ASYNC16(sa, ga);
        }
    };

    float acc[4][8][4];
    #pragma unroll
    for (int mt = 0; mt < 4; mt++)
        #pragma unroll
        for (int nt = 0; nt < 8; nt++)
            #pragma unroll
            for (int r = 0; r < 4; r++) acc[mt][nt][r] = 0.f;

    const int kt = Kdim >> 5;                        // BK = 32

    load_stage(0, 0);
    CP_COMMIT();

    for (int i = 0; i < kt; i++) {
        const int cur = i & 1;
        if (i + 1 < kt) { load_stage(cur ^ 1, i + 1); CP_COMMIT(); CP_WAIT(1); }
        else            { CP_WAIT(0); }
        __syncthreads();

        const uint32_t sb = sbase + cur * STAGE_SM;
        #pragma unroll
        for (int ks = 0; ks < 2; ks++) {             // two k16 halves of BK=32
            // preload ALL fragments for this k16 step
            uint32_t ah[4][4], alr[4][4];
            #pragma unroll
            for (int mt = 0; mt < 4; mt++) {
                uint32_t ra = sb + (wm * 64 + mt * 16 + (lane & 15)) * TSTRIDE
                            + ks * 32 + ((lane >> 4) << 4);
                ldsm4(ah[mt],  ra);
                ldsm4(alr[mt], ra + TILE_SM);
            }
            uint32_t bh4[4][4], bl4[4][4];
            #pragma unroll
            for (int nt2 = 0; nt2 < 4; nt2++) {
                uint32_t rb = sb + 2 * TILE_SM
                            + (wn * 64 + nt2 * 16 + ((lane & 7) + ((lane >> 4) << 3))) * TSTRIDE
                            + ks * 32 + (((lane >> 3) & 1) << 4);
                ldsm4(bh4[nt2], rb);
                ldsm4(bl4[nt2], rb + TILE_SM);
            }
            // product loop OUTERMOST: same-accumulator reuse distance = 32 MMAs
            #pragma unroll
            for (int p = 0; p < 3; p++) {
                #pragma unroll
                for (int mt = 0; mt < 4; mt++)
                    #pragma unroll
                    for (int nt2 = 0; nt2 < 4; nt2++)
                        #pragma unroll
                        for (int nn = 0; nn < 2; nn++) {
                            float* c = acc[mt][nt2 * 2 + nn];
                            const uint32_t* a = (p == 2) ? alr[mt] : ah[mt];
                            const uint32_t* bb = (p == 1) ? bl4[nt2] : bh4[nt2];
                            mma_bf16(c, a, bb[2 * nn], bb[2 * nn + 1]);
                        }
            }
        }
        __syncthreads();
    }

    // epilogue
    const int grp = lane >> 2, tig = lane & 3;
    #pragma unroll
    for (int mt = 0; mt < 4; mt++) {
        #pragma unroll
        for (int half = 0; half < 2; half++) {
            const size_t row = orow + wm * 64 + mt * 16 + grp + half * 8;
            #pragma unroll
            for (int nt = 0; nt < 8; nt++) {
                const int col = n0 + wn * 64 + nt * 8 + tig * 2;
                float v0 = acc[mt][nt][half * 2 + 0];
                float v1 = acc[mt][nt][half * 2 + 1];
                if (outF) {
                    *(float2*)&outF[row * ldo + col] = make_float2(v0 * scale, v1 * scale);
                } else {
                    if (addb) { v0 += bias[col]; v1 += bias[col + 1]; }
                    __nv_bfloat16 h0, l0, h1, l1;
                    split2(v0, h0, l0); split2(v1, h1, l1);
                    *(uint32_t*)&oHi[row * ldo + col] = packbf(h0, h1);
                    *(uint32_t*)&oLo[row * ldo + col] = packbf(l0, l1);
                }
            }
        }
    }
}

// ---------------- kernel: V projection (SIMT fp32), transposed split output --
__global__ __launch_bounds__(256) void v_gemm(
    const float* __restrict__ X, const float* __restrict__ W,
    const float* __restrict__ bias, const int* __restrict__ seq)
{
    const int tid = threadIdx.x;
    const int tx = tid & 15;
    const int ty = tid >> 4;

    const int b    = blockIdx.y >> 4;
    const int tloc = (blockIdx.y & 15) << 7;
    const int col0 = blockIdx.x << 7;
    const int first = seq_first(seq, b);
    if (tloc >= first) return;

    const int xrow0 = b * SS + tloc;

    __shared__ float As[16][128];
    __shared__ float Bs[16][128];

    float acc[8][8];
    #pragma unroll
    for (int i = 0; i < 8; i++)
        #pragma unroll
        for (int j = 0; j < 8; j++) acc[i][j] = 0.f;

    for (int k0 = 0; k0 < EE; k0 += 16) {
        #pragma unroll
        for (int v = tid; v < 512; v += 256) {
            int r = v >> 2;
            int c = (v & 3) << 2;
            float4 a = *(const float4*)&X[(size_t)(xrow0 + r) * EE + k0 + c];
            As[c + 0][r] = a.x; As[c + 1][r] = a.y;
            As[c + 2][r] = a.z; As[c + 3][r] = a.w;
            float4 wv = *(const float4*)&W[(size_t)(col0 + r) * EE + k0 + c];
            Bs[c + 0][r] = wv.x; Bs[c + 1][r] = wv.y;
            Bs[c + 2][r] = wv.z; Bs[c + 3][r] = wv.w;
        }
        __syncthreads();

        #pragma unroll
        for (int kk = 0; kk < 16; kk++) {
            float4 a0 = *(const float4*)&As[kk][ty * 8];
            float4 a1 = *(const float4*)&As[kk][ty * 8 + 4];
            float4 b0 = *(const float4*)&Bs[kk][tx * 8];
            float4 b1 = *(const float4*)&Bs[kk][tx * 8 + 4];
            float av[8] = {a0.x, a0.y, a0.z, a0.w, a1.x, a1.y, a1.z, a1.w};
            float bv[8] = {b0.x, b0.y, b0.z, b0.w, b1.x, b1.y, b1.z, b1.w};
            #pragma unroll
            for (int i = 0; i < 8; i++)
                #pragma unroll
                for (int j = 0; j < 8; j++)
                    acc[i][j] = fmaf(av[i], bv[j], acc[i][j]);
        }
        __syncthreads();
    }

    // transposed split write: Vt[b][e][token]
    const int tok0 = tloc + ty * 8;
    #pragma unroll
    for (int j = 0; j < 8; j++) {
        const int e = col0 + tx * 8 + j;
        const float be = bias[e];
        uint32_t hu[4], lu[4];
        #pragma unroll
        for (int pr = 0; pr < 4; pr++) {
            __nv_bfloat16 h0, l0, h1, l1;
            split2(acc[pr * 2 + 0][j] + be, h0, l0);
            split2(acc[pr * 2 + 1][j] + be, h1, l1);
            hu[pr] = packbf(h0, h1);
            lu[pr] = packbf(l0, l1);
        }
        const size_t off = ((size_t)b * EE + e) * JMAX + tok0;
        *(uint4*)&g_Vth[off] = make_uint4(hu[0], hu[1], hu[2], hu[3]);
        *(uint4*)&g_Vtl[off] = make_uint4(lu[0], lu[1], lu[2], lu[3]);
    }
}

// ---------------- kernel: masked softmax -> split bf16 P ---------------------
__global__ __launch_bounds__(256) void softmax_rows(const int* __restrict__ seq)
{
    const int b = blockIdx.x >> 12;
    const int q = blockIdx.x & 4095;
    const int first = seq_first(seq, b);
    const float* row = g_P + ((size_t)b * SS + q) * JMAX;
    const int tid = threadIdx.x;

    __shared__ float red[256];

    float m = -1e30f;
    for (int j = 1 + tid; j < first; j += 256) m = fmaxf(m, row[j]);
    red[tid] = m;
    __syncthreads();
    #pragma unroll
    for (int s = 128; s > 0; s >>= 1) {
        if (tid < s) red[tid] = fmaxf(red[tid], red[tid + s]);
        __syncthreads();
    }
    m = red[0];
    __syncthreads();

    float l = 0.f;
    for (int j = 1 + tid; j < first; j += 256) l += expf(row[j] - m);
    red[tid] = l;
    __syncthreads();
    #pragma unroll
    for (int s = 128; s > 0; s >>= 1) {
        if (tid < s) red[tid] += red[tid + s];
        __syncthreads();
    }
    const float inv = 1.0f / red[0];

    const int kpad = (first + 63) & ~63;
    const size_t ro = ((size_t)b * SS + q) * JMAX;
    for (int j = tid; j < kpad; j += 256) {
        float p = 0.f;
        if (j >= 1 && j < first) p = expf(row[j] - m) * inv;
        __nv_bfloat16 h, lo;
        split2(p, h, lo);
        g_Phi[ro + j] = h;
        g_Plo[ro + j] = lo;
    }
}

// ---------------------------------------------------------------------------
extern "C" void kernel_launch(void* const* d_in, const int* in_sizes, int n_in,
                              void* d_out, int out_size)
{
    const float* ebd = (const float*)d_in[0];
    const int*   seq = (const int*)d_in[1];
    const float* Wq = (const float*)d_in[2];
    const float* bq = (const float*)d_in[3];
    const float* Wk = (const float*)d_in[4];
    const float* bk = (const float*)d_in[5];
    const float* Wv = (const float*)d_in[6];
    const float* bv = (const float*)d_in[7];
    float* H = (float*)d_out;

    static cudaStream_t s2 = nullptr;
    static cudaEvent_t evFork = nullptr, evJoin = nullptr;
    if (!s2) {
        cudaFuncSetAttribute(tc_gemm, cudaFuncAttributeMaxDynamicSharedMemorySize, SMEM_TC);
        cudaStreamCreateWithFlags(&s2, cudaStreamNonBlocking);
        cudaEventCreateWithFlags(&evFork, cudaEventDisableTiming);
        cudaEventCreateWithFlags(&evJoin, cudaEventDisableTiming);
    }

    // fork: v_gemm (independent of everything until PV) on side stream
    cudaEventRecord(evFork, 0);
    cudaStreamWaitEvent(s2, evFork, 0);
    v_gemm<<<dim3(EE / 128, BB * (JMAX / 128)), 256, 0, s2>>>(ebd, Wv, bv, seq);
    cudaEventRecord(evJoin, s2);

    // 0) fp32 -> split bf16 for X, Wq, Wk
    {
        size_t n4 = NX / 4;
        split_sel<<<(unsigned)((n4 + 255) / 256), 256>>>(ebd, 0, n4);
        size_t w4 = (size_t)EE * EE / 4;
        split_sel<<<(unsigned)((w4 + 255) / 256), 256>>>(Wq, 1, w4);
        split_sel<<<(unsigned)((w4 + 255) / 256), 256>>>(Wk, 2, w4);
    }

    // 1) projections
    tc_gemm<<<dim3(EE / 128, BB * SS / 128, 1), 128, SMEM_TC>>>(MODE_PROJQ, seq, bq, nullptr);
    tc_gemm<<<dim3(EE / 128, BB * (JMAX / 128), 1), 128, SMEM_TC>>>(MODE_PROJK, seq, bk, nullptr);

    // 2) scores (fp32 out)
    tc_gemm<<<dim3(JMAX / 128, SS / 128, BB), 128, SMEM_TC>>>(MODE_SCORE, seq, nullptr, nullptr);

    // 3) masked softmax -> split bf16 P
    softmax_rows<<<BB * SS, 256>>>(seq);

    // join: PV needs g_Vth/g_Vtl
    cudaStreamWaitEvent(0, evJoin, 0);

    // 4) H = P @ V
    tc_gemm<<<dim3(EE / 128, SS / 128, BB), 128, SMEM_TC>>>(MODE_PV, seq, nullptr, H);
}

// round 8
// speedup vs baseline: 2.4999x; 1.0348x over previous
#include <cuda_runtime.h>
#include <cuda_bf16.h>
#include <cstdint>

#define BB 8
#define SS 4096
#define EE 768
#define JMAX 2048
#define INV_SQRT_DK 0.03608439182435161f

#define NX ((size_t)BB * SS * EE)     // 25.2M
#define NK ((size_t)BB * JMAX * EE)   // 12.6M
#define NP ((size_t)BB * SS * JMAX)   // 67.1M

// ---------------- scratch (device globals; no allocations allowed) ----------
__device__ __nv_bfloat16 g_Xhi[NX], g_Xlo[NX];
__device__ __nv_bfloat16 g_Wqh[EE * EE], g_Wql[EE * EE];
__device__ __nv_bfloat16 g_Wkh[EE * EE], g_Wkl[EE * EE];
__device__ __nv_bfloat16 g_Qhi[NX], g_Qlo[NX];
__device__ __nv_bfloat16 g_Khi[NK], g_Klo[NK];
__device__ __nv_bfloat16 g_Vth[NK], g_Vtl[NK];   // [b][e][token] transposed V splits
__device__ float g_P[NP];
__device__ __nv_bfloat16 g_Phi[NP], g_Plo[NP];   // unnormalized exp splits
__device__ float g_invl[BB * SS];                 // per-row 1/sum

// ---------------- helpers ----------------------------------------------------
__device__ __forceinline__ uint32_t smem_to_u32(const void* p) {
    uint32_t a;
    asm("{ .reg .u64 t; cvta.to.shared.u64 t, %1; cvt.u32.u64 %0, t; }" : "=r"(a) : "l"(p));
    return a;
}
__device__ __forceinline__ int seq_first(const int* __restrict__ s, int b) {
    const bool is64 = (s[1] == 0);
    int v = is64 ? s[4 * b] : s[2 * b];
    if (v < 1) v = 1;
    if (v > JMAX) v = JMAX;
    return v;
}
__device__ __forceinline__ void split2(float v, __nv_bfloat16& h, __nv_bfloat16& l) {
    h = __float2bfloat16(v);
    l = __float2bfloat16(v - __bfloat162float(h));
}
__device__ __forceinline__ uint32_t packbf(__nv_bfloat16 a, __nv_bfloat16 b) {
    return (uint32_t)__bfloat16_as_ushort(a) | ((uint32_t)__bfloat16_as_ushort(b) << 16);
}

__device__ __forceinline__ void ldsm4(uint32_t* d, uint32_t a) {
    asm volatile("ldmatrix.sync.aligned.m8n8.x4.shared.b16 {%0,%1,%2,%3}, [%4];"
                 : "=r"(d[0]), "=r"(d[1]), "=r"(d[2]), "=r"(d[3]) : "r"(a));
}
__device__ __forceinline__ void mma_bf16(float* c, const uint32_t* a, uint32_t b0, uint32_t b1) {
    asm volatile(
        "mma.sync.aligned.m16n8k16.row.col.f32.bf16.bf16.f32 "
        "{%0,%1,%2,%3}, {%4,%5,%6,%7}, {%8,%9}, {%0,%1,%2,%3};"
        : "+f"(c[0]), "+f"(c[1]), "+f"(c[2]), "+f"(c[3])
        : "r"(a[0]), "r"(a[1]), "r"(a[2]), "r"(a[3]), "r"(b0), "r"(b1));
}
#define CP_ASYNC16(sa, ga) \
    asm volatile("cp.async.cg.shared.global [%0], [%1], 16;" :: "r"(sa), "l"(ga) : "memory")
#define CP_COMMIT() asm volatile("cp.async.commit_group;" ::: "memory")
#define CP_WAIT(n)  asm volatile("cp.async.wait_group %0;" :: "n"(n) : "memory")

// ---------------- kernel: fp32 -> (hi, lo) bf16 splits ------------------------
__global__ __launch_bounds__(256) void split_sel(const float* __restrict__ src,
                                                 int sel, size_t n4)
{
    size_t i = (size_t)blockIdx.x * 256 + threadIdx.x;
    if (i >= n4) return;
    __nv_bfloat16 *dh, *dl;
    if (sel == 0)      { dh = g_Xhi; dl = g_Xlo; }
    else if (sel == 1) { dh = g_Wqh; dl = g_Wql; }
    else               { dh = g_Wkh; dl = g_Wkl; }
    float4 v = ((const float4*)src)[i];
    __nv_bfloat16 h0, l0, h1, l1, h2, l2, h3, l3;
    split2(v.x, h0, l0); split2(v.y, h1, l1);
    split2(v.z, h2, l2); split2(v.w, h3, l3);
    ((uint2*)dh)[i] = make_uint2(packbf(h0, h1), packbf(h2, h3));
    ((uint2*)dl)[i] = make_uint2(packbf(l0, l1), packbf(l2, l3));
}

// ---------------- generic split-bf16 NT GEMM on mma.sync ---------------------
// D[128x128] = (Ahi+Alo)[128xK] * (Bhi+Blo)[128xK]^T  (3 bf16 products, f32 acc)
// 128 threads (4 warps, 2x2 grid, 64x64 warp tile), 2 CTAs/SM.
#define TSTRIDE 80
#define TILE_SM (128 * TSTRIDE)          // 10240
#define STAGE_SM (4 * TILE_SM)           // 40960
#define SMEM_TC (2 * STAGE_SM)           // 81920

#define MODE_PROJQ 0
#define MODE_PROJK 1
#define MODE_SCORE 2
#define MODE_PV    3

__global__ __launch_bounds__(128, 2) void tc_gemm(int mode, const int* __restrict__ seq,
                                                  const float* __restrict__ bias,
                                                  float* __restrict__ Hout)
{
    const int n0 = blockIdx.x << 7;
    int b = 0, first = 0, Kdim = EE;
    size_t arow, brow, orow;
    int lda, ldb, ldo = EE;
    const __nv_bfloat16 *Ah, *Al, *Bh, *Bl;
    float* outF = nullptr;
    __nv_bfloat16 *oHi = nullptr, *oLo = nullptr;
    float scale = 1.f;
    bool addb = false;

    if (mode == MODE_PROJQ) {
        arow = (size_t)blockIdx.y << 7; brow = n0; orow = arow;
        Ah = g_Xhi; Al = g_Xlo; lda = EE; Bh = g_Wqh; Bl = g_Wql; ldb = EE;
        oHi = g_Qhi; oLo = g_Qlo; ldo = EE; addb = true;
    } else if (mode == MODE_PROJK) {
        b = blockIdx.y >> 4;
        int tloc = (blockIdx.y & 15) << 7;
        first = seq_first(seq, b);
        if (tloc >= first) return;
        arow = (size_t)b * SS + tloc; brow = n0; orow = (size_t)b * JMAX + tloc;
        Ah = g_Xhi; Al = g_Xlo; lda = EE; Bh = g_Wkh; Bl = g_Wkl; ldb = EE;
        oHi = g_Khi; oLo = g_Klo; ldo = EE; addb = true;
    } else if (mode == MODE_SCORE) {
        b = blockIdx.z; first = seq_first(seq, b);
        if (n0 >= first) return;
        arow = (size_t)b * SS + ((size_t)blockIdx.y << 7);
        brow = (size_t)b * JMAX + n0;
        Ah = g_Qhi; Al = g_Qlo; lda = EE; Bh = g_Khi; Bl = g_Klo; ldb = EE;
        outF = g_P; ldo = JMAX; orow = arow; scale = INV_SQRT_DK;
    } else { // MODE_PV
        b = blockIdx.z; first = seq_first(seq, b);
        Kdim = (first + 63) & ~63;
        arow = (size_t)b * SS + ((size_t)blockIdx.y << 7);
        brow = (size_t)b * EE + n0;
        Ah = g_Phi; Al = g_Plo; lda = JMAX; Bh = g_Vth; Bl = g_Vtl; ldb = JMAX;
        outF = Hout; ldo = EE; orow = arow;
    }

    extern __shared__ char smem[];
    const uint32_t sbase = smem_to_u32(smem);
    const int tid  = threadIdx.x;
    const int lane = tid & 31, wid = tid >> 5;
    const int wm = wid >> 1, wn = wid & 1;          // 2 x 2 warp grid, warp tile 64x64

    const char* gsrc[4] = { (const char*)(Ah + arow * lda), (const char*)(Al + arow * lda),
                            (const char*)(Bh + brow * ldb), (const char*)(Bl + brow * ldb) };
    const size_t ldby[4] = { (size_t)lda * 2, (size_t)lda * 2,
                             (size_t)ldb * 2, (size_t)ldb * 2 };

    auto load_stage = [&](int s, int ki) {
        const size_t k0b = (size_t)ki * 64;          // 32 bf16 = 64 bytes
        const uint32_t sb = sbase + s * STAGE_SM;
        #pragma unroll
        for (int j = 0; j < 16; j++) {
            int t = tid + j * 128;                   // 2048 chunks of 16B
            int tile = t >> 9, row = (t >> 2) & 127, c = t & 3;
            uint32_t sa = sb + tile * TILE_SM + row * TSTRIDE + c * 16;
            const char* ga = gsrc[tile] + (size_t)row * ldby[tile] + k0b + c * 16;
            CP_ASYNC16(sa, ga);
        }
    };

    float acc[4][8][4];
    #pragma unroll
    for (int mt = 0; mt < 4; mt++)
        #pragma unroll
        for (int nt = 0; nt < 8; nt++)
            #pragma unroll
            for (int r = 0; r < 4; r++) acc[mt][nt][r] = 0.f;

    const int kt = Kdim >> 5;                        // BK = 32

    load_stage(0, 0);
    CP_COMMIT();

    for (int i = 0; i < kt; i++) {
        const int cur = i & 1;
        if (i + 1 < kt) { load_stage(cur ^ 1, i + 1); CP_COMMIT(); CP_WAIT(1); }
        else            { CP_WAIT(0); }
        __syncthreads();

        const uint32_t sb = sbase + cur * STAGE_SM;
        #pragma unroll
        for (int ks = 0; ks < 2; ks++) {             // two k16 halves of BK=32
            uint32_t ah[4][4], alr[4][4];
            #pragma unroll
            for (int mt = 0; mt < 4; mt++) {
                uint32_t ra = sb + (wm * 64 + mt * 16 + (lane & 15)) * TSTRIDE
                            + ks * 32 + ((lane >> 4) << 4);
                ldsm4(ah[mt],  ra);
                ldsm4(alr[mt], ra + TILE_SM);
            }
            uint32_t bh4[4][4], bl4[4][4];
            #pragma unroll
            for (int nt2 = 0; nt2 < 4; nt2++) {
                uint32_t rb = sb + 2 * TILE_SM
                            + (wn * 64 + nt2 * 16 + ((lane & 7) + ((lane >> 4) << 3))) * TSTRIDE
                            + ks * 32 + (((lane >> 3) & 1) << 4);
                ldsm4(bh4[nt2], rb);
                ldsm4(bl4[nt2], rb + TILE_SM);
            }
            #pragma unroll
            for (int p = 0; p < 3; p++) {
                #pragma unroll
                for (int mt = 0; mt < 4; mt++)
                    #pragma unroll
                    for (int nt2 = 0; nt2 < 4; nt2++)
                        #pragma unroll
                        for (int nn = 0; nn < 2; nn++) {
                            float* c = acc[mt][nt2 * 2 + nn];
                            const uint32_t* a = (p == 2) ? alr[mt] : ah[mt];
                            const uint32_t* bb = (p == 1) ? bl4[nt2] : bh4[nt2];
                            mma_bf16(c, a, bb[2 * nn], bb[2 * nn + 1]);
                        }
            }
        }
        __syncthreads();
    }

    // epilogue
    const int grp = lane >> 2, tig = lane & 3;
    #pragma unroll
    for (int mt = 0; mt < 4; mt++) {
        #pragma unroll
        for (int half = 0; half < 2; half++) {
            const size_t row = orow + wm * 64 + mt * 16 + grp + half * 8;
            float rsc = scale;
            if (mode == MODE_PV) rsc = g_invl[row];
            #pragma unroll
            for (int nt = 0; nt < 8; nt++) {
                const int col = n0 + wn * 64 + nt * 8 + tig * 2;
                float v0 = acc[mt][nt][half * 2 + 0];
                float v1 = acc[mt][nt][half * 2 + 1];
                if (outF) {
                    *(float2*)&outF[row * ldo + col] = make_float2(v0 * rsc, v1 * rsc);
                } else {
                    if (addb) { v0 += bias[col]; v1 += bias[col + 1]; }
                    __nv_bfloat16 h0, l0, h1, l1;
                    split2(v0, h0, l0); split2(v1, h1, l1);
                    *(uint32_t*)&oHi[row * ldo + col] = packbf(h0, h1);
                    *(uint32_t*)&oLo[row * ldo + col] = packbf(l0, l1);
                }
            }
        }
    }
}

// ---------------- kernel: V projection (SIMT fp32), transposed split output --
__global__ __launch_bounds__(256) void v_gemm(
    const float* __restrict__ X, const float* __restrict__ W,
    const float* __restrict__ bias, const int* __restrict__ seq)
{
    const int tid = threadIdx.x;
    const int tx = tid & 15;
    const int ty = tid >> 4;

    const int b    = blockIdx.y >> 4;
    const int tloc = (blockIdx.y & 15) << 7;
    const int col0 = blockIdx.x << 7;
    const int first = seq_first(seq, b);
    if (tloc >= first) return;

    const int xrow0 = b * SS + tloc;

    __shared__ float As[16][128];
    __shared__ float Bs[16][128];

    float acc[8][8];
    #pragma unroll
    for (int i = 0; i < 8; i++)
        #pragma unroll
        for (int j = 0; j < 8; j++) acc[i][j] = 0.f;

    for (int k0 = 0; k0 < EE; k0 += 16) {
        #pragma unroll
        for (int v = tid; v < 512; v += 256) {
            int r = v >> 2;
            int c = (v & 3) << 2;
            float4 a = *(const float4*)&X[(size_t)(xrow0 + r) * EE + k0 + c];
            As[c + 0][r] = a.x; As[c + 1][r] = a.y;
            As[c + 2][r] = a.z; As[c + 3][r] = a.w;
            float4 wv = *(const float4*)&W[(size_t)(col0 + r) * EE + k0 + c];
            Bs[c + 0][r] = wv.x; Bs[c + 1][r] = wv.y;
            Bs[c + 2][r] = wv.z; Bs[c + 3][r] = wv.w;
        }
        __syncthreads();

        #pragma unroll
        for (int kk = 0; kk < 16; kk++) {
            float4 a0 = *(const float4*)&As[kk][ty * 8];
            float4 a1 = *(const float4*)&As[kk][ty * 8 + 4];
            float4 b0 = *(const float4*)&Bs[kk][tx * 8];
            float4 b1 = *(const float4*)&Bs[kk][tx * 8 + 4];
            float av[8] = {a0.x, a0.y, a0.z, a0.w, a1.x, a1.y, a1.z, a1.w};
            float bv[8] = {b0.x, b0.y, b0.z, b0.w, b1.x, b1.y, b1.z, b1.w};
            #pragma unroll
            for (int i = 0; i < 8; i++)
                #pragma unroll
                for (int j = 0; j < 8; j++)
                    acc[i][j] = fmaf(av[i], bv[j], acc[i][j]);
        }
        __syncthreads();
    }

    const int tok0 = tloc + ty * 8;
    #pragma unroll
    for (int j = 0; j < 8; j++) {
        const int e = col0 + tx * 8 + j;
        const float be = bias[e];
        uint32_t hu[4], lu[4];
        #pragma unroll
        for (int pr = 0; pr < 4; pr++) {
            __nv_bfloat16 h0, l0, h1, l1;
            split2(acc[pr * 2 + 0][j] + be, h0, l0);
            split2(acc[pr * 2 + 1][j] + be, h1, l1);
            hu[pr] = packbf(h0, h1);
            lu[pr] = packbf(l0, l1);
        }
        const size_t off = ((size_t)b * EE + e) * JMAX + tok0;
        *(uint4*)&g_Vth[off] = make_uint4(hu[0], hu[1], hu[2], hu[3]);
        *(uint4*)&g_Vtl[off] = make_uint4(lu[0], lu[1], lu[2], lu[3]);
    }
}

// ---------------- kernel: masked softmax (2-pass, unnormalized exp out) ------
__global__ __launch_bounds__(256) void softmax_rows(const int* __restrict__ seq)
{
    const int b = blockIdx.x >> 12;
    const int q = blockIdx.x & 4095;
    const int first = seq_first(seq, b);
    const float* row = g_P + ((size_t)b * SS + q) * JMAX;
    const int tid = threadIdx.x;

    __shared__ float red[256];

    float m = -1e30f;
    for (int j = 1 + tid; j < first; j += 256) m = fmaxf(m, row[j]);
    red[tid] = m;
    __syncthreads();
    #pragma unroll
    for (int s = 128; s > 0; s >>= 1) {
        if (tid < s) red[tid] = fmaxf(red[tid], red[tid + s]);
        __syncthreads();
    }
    m = red[0];
    __syncthreads();

    // pass 2: write unnormalized exp splits, accumulate l
    const int kpad = (first + 63) & ~63;
    const size_t ro = ((size_t)b * SS + q) * JMAX;
    float l = 0.f;
    for (int j = tid; j < kpad; j += 256) {
        float p = 0.f;
        if (j >= 1 && j < first) { p = __expf(row[j] - m); l += p; }
        __nv_bfloat16 h, lo;
        split2(p, h, lo);
        g_Phi[ro + j] = h;
        g_Plo[ro + j] = lo;
    }
    red[tid] = l;
    __syncthreads();
    #pragma unroll
    for (int s = 128; s > 0; s >>= 1) {
        if (tid < s) red[tid] += red[tid + s];
        __syncthreads();
    }
    if (tid == 0) g_invl[b * SS + q] = 1.0f / fmaxf(red[0], 1e-30f);
}

// ---------------------------------------------------------------------------
extern "C" void kernel_launch(void* const* d_in, const int* in_sizes, int n_in,
                              void* d_out, int out_size)
{
    const float* ebd = (const float*)d_in[0];
    const int*   seq = (const int*)d_in[1];
    const float* Wq = (const float*)d_in[2];
    const float* bq = (const float*)d_in[3];
    const float* Wk = (const float*)d_in[4];
    const float* bk = (const float*)d_in[5];
    const float* Wv = (const float*)d_in[6];
    const float* bv = (const float*)d_in[7];
    float* H = (float*)d_out;

    static cudaStream_t s2 = nullptr;
    static cudaEvent_t evFork = nullptr, evSplit = nullptr, evJoin = nullptr;
    if (!s2) {
        cudaFuncSetAttribute(tc_gemm, cudaFuncAttributeMaxDynamicSharedMemorySize, SMEM_TC);
        cudaStreamCreateWithFlags(&s2, cudaStreamNonBlocking);
        cudaEventCreateWithFlags(&evFork, cudaEventDisableTiming);
        cudaEventCreateWithFlags(&evSplit, cudaEventDisableTiming);
        cudaEventCreateWithFlags(&evJoin, cudaEventDisableTiming);
    }

    // fork: v_gemm (no deps) on side stream
    cudaEventRecord(evFork, 0);
    cudaStreamWaitEvent(s2, evFork, 0);
    v_gemm<<<dim3(EE / 128, BB * (JMAX / 128)), 256, 0, s2>>>(ebd, Wv, bv, seq);

    // 0) fp32 -> split bf16 for X, Wq, Wk (main stream)
    {
        size_t n4 = NX / 4;
        split_sel<<<(unsigned)((n4 + 255) / 256), 256>>>(ebd, 0, n4);
        size_t w4 = (size_t)EE * EE / 4;
        split_sel<<<(unsigned)((w4 + 255) / 256), 256>>>(Wq, 1, w4);
        split_sel<<<(unsigned)((w4 + 255) / 256), 256>>>(Wk, 2, w4);
    }
    cudaEventRecord(evSplit, 0);

    // PROJK on side stream (after splits), PROJQ on main — overlap
    cudaStreamWaitEvent(s2, evSplit, 0);
    tc_gemm<<<dim3(EE / 128, BB * (JMAX / 128), 1), 128, SMEM_TC, s2>>>(MODE_PROJK, seq, bk, nullptr);
    cudaEventRecord(evJoin, s2);

    tc_gemm<<<dim3(EE / 128, BB * SS / 128, 1), 128, SMEM_TC>>>(MODE_PROJQ, seq, bq, nullptr);

    // join: SCORE needs K (and later PV needs V, ordered before PROJK on s2)
    cudaStreamWaitEvent(0, evJoin, 0);

    // 2) scores (fp32 out)
    tc_gemm<<<dim3(JMAX / 128, SS / 128, BB), 128, SMEM_TC>>>(MODE_SCORE, seq, nullptr, nullptr);

    // 3) masked softmax -> unnormalized split exp + inv_l
    softmax_rows<<<BB * SS, 256>>>(seq);

    // 4) H = (P @ V) * inv_l
    tc_gemm<<<dim3(EE / 128, SS / 128, BB), 128, SMEM_TC>>>(MODE_PV, seq, nullptr, H);
}